// round 1
// baseline (speedup 1.0000x reference)
#include <cuda_runtime.h>

#define B 8
#define C 256
#define HW 4096
#define BN_EPS 1e-5f
#define SPLIT 8
#define CHUNK (HW / SPLIT)   // 512

// Scratch (device globals; no runtime allocation allowed)
__device__ float g_Y[3][(size_t)B * C * HW];      // projections q,k,v
__device__ float g_a[3][C];                        // BN affine scale
__device__ float g_d[3][C];                        // BN affine shift
__device__ float g_Mpart[SPLIT][(size_t)B * C * C];
__device__ float g_M[(size_t)B * C * C];

// ---------------------------------------------------------------------------
// K1: projection GEMM.  Y[p][b,o,n] = sum_c W_p[o,c] * x[b,c,n] + bias_p[o]
// grid: (HW/64, C/64, 3*B), block 256, 64x64 tile, 4x4 per thread, BK=16
// ---------------------------------------------------------------------------
__global__ __launch_bounds__(256) void proj_gemm(
    const float* __restrict__ x,
    const float* __restrict__ Wq, const float* __restrict__ bq,
    const float* __restrict__ Wk, const float* __restrict__ bk,
    const float* __restrict__ Wv, const float* __restrict__ bv)
{
    __shared__ float Ws[16][64];   // [k][m]
    __shared__ float Xs[16][64];   // [k][n]

    const int p = blockIdx.z / B;
    const int b = blockIdx.z % B;
    const float* W    = (p == 0) ? Wq : (p == 1) ? Wk : Wv;
    const float* bias = (p == 0) ? bq : (p == 1) ? bk : bv;
    const float* xb = x + (size_t)b * C * HW;
    float* Yb = &g_Y[p][(size_t)b * C * HW];

    const int tid = threadIdx.x;
    const int n0 = blockIdx.x * 64;
    const int m0 = blockIdx.y * 64;
    const int tx = tid & 15, ty = tid >> 4;
    const int wrow = tid >> 2, wcol = (tid & 3) * 4;   // W loader: 64 rows x 16 k
    const int xrow = tid >> 4, xcol = (tid & 15) * 4;  // X loader: 16 k x 64 n

    float acc[4][4] = {};

    for (int k0 = 0; k0 < C; k0 += 16) {
        float4 wv = *(const float4*)&W[(size_t)(m0 + wrow) * C + k0 + wcol];
        float4 xv = *(const float4*)&xb[(size_t)(k0 + xrow) * HW + n0 + xcol];
        __syncthreads();
        Ws[wcol + 0][wrow] = wv.x; Ws[wcol + 1][wrow] = wv.y;
        Ws[wcol + 2][wrow] = wv.z; Ws[wcol + 3][wrow] = wv.w;
        *(float4*)&Xs[xrow][xcol] = xv;
        __syncthreads();
        #pragma unroll
        for (int k = 0; k < 16; k++) {
            float4 a4 = *(const float4*)&Ws[k][ty * 4];
            float4 b4 = *(const float4*)&Xs[k][tx * 4];
            float av[4] = {a4.x, a4.y, a4.z, a4.w};
            float bv2[4] = {b4.x, b4.y, b4.z, b4.w};
            #pragma unroll
            for (int i = 0; i < 4; i++)
                #pragma unroll
                for (int j = 0; j < 4; j++)
                    acc[i][j] += av[i] * bv2[j];
        }
    }

    #pragma unroll
    for (int i = 0; i < 4; i++) {
        float bi = bias[m0 + ty * 4 + i];
        #pragma unroll
        for (int j = 0; j < 4; j++)
            Yb[(size_t)(m0 + ty * 4 + i) * HW + n0 + tx * 4 + j] = acc[i][j] + bi;
    }
}

// ---------------------------------------------------------------------------
// K2: BN batch stats per (projection, channel) over (b, h, w) = 32768 elems.
// Deterministic tree reduction. Produces affine a = g*rsqrt(var+eps),
// d = beta - mu*a.  grid: 3*C blocks of 256.
// ---------------------------------------------------------------------------
__global__ __launch_bounds__(256) void bn_stats(
    const float* __restrict__ gq, const float* __restrict__ betaq,
    const float* __restrict__ gk, const float* __restrict__ betak,
    const float* __restrict__ gv, const float* __restrict__ betav)
{
    __shared__ float rs[256], rs2[256];
    const int p = blockIdx.x / C;
    const int c = blockIdx.x % C;
    const int tid = threadIdx.x;

    float s = 0.f, s2 = 0.f;
    for (int b = 0; b < B; b++) {
        const float4* ptr = (const float4*)&g_Y[p][((size_t)b * C + c) * HW];
        for (int i = tid; i < HW / 4; i += 256) {
            float4 v = ptr[i];
            s  += v.x + v.y + v.z + v.w;
            s2 += v.x * v.x + v.y * v.y + v.z * v.z + v.w * v.w;
        }
    }
    rs[tid] = s; rs2[tid] = s2;
    __syncthreads();
    for (int off = 128; off > 0; off >>= 1) {
        if (tid < off) { rs[tid] += rs[tid + off]; rs2[tid] += rs2[tid + off]; }
        __syncthreads();
    }
    if (tid == 0) {
        const float inv_n = 1.f / (float)(B * HW);
        float mu  = rs[0] * inv_n;
        float var = rs2[0] * inv_n - mu * mu;
        float inv = rsqrtf(var + BN_EPS);
        const float* g  = (p == 0) ? gq : (p == 1) ? gk : gv;
        const float* be = (p == 0) ? betaq : (p == 1) ? betak : betav;
        float a = g[c] * inv;
        g_a[p][c] = a;
        g_d[p][c] = be[c] - mu * a;
    }
}

// ---------------------------------------------------------------------------
// K3: M[b,cv,ck] = sum_n Vn[b,cv,n]*Kn[b,ck,n], affine applied at load.
// Split-K over n (SPLIT chunks, deterministic partials).
// grid: (C/64, C/64, SPLIT*B), block 256.
// ---------------------------------------------------------------------------
__global__ __launch_bounds__(256) void m_gemm()
{
    __shared__ float Vs[16][64];
    __shared__ float Ks[16][64];

    const int s = blockIdx.z / B;
    const int b = blockIdx.z % B;
    const int m0 = blockIdx.y * 64;   // cv
    const int n0 = blockIdx.x * 64;   // ck
    const float* Kb = &g_Y[1][(size_t)b * C * HW];
    const float* Vb = &g_Y[2][(size_t)b * C * HW];

    const int tid = threadIdx.x;
    const int tx = tid & 15, ty = tid >> 4;
    const int row = tid >> 2, col = (tid & 3) * 4;

    const float av = g_a[2][m0 + row], dv = g_d[2][m0 + row];
    const float ak = g_a[1][n0 + row], dk = g_d[1][n0 + row];

    float acc[4][4] = {};
    const int kbase = s * CHUNK;
    for (int kk = kbase; kk < kbase + CHUNK; kk += 16) {
        float4 vv = *(const float4*)&Vb[(size_t)(m0 + row) * HW + kk + col];
        float4 kv = *(const float4*)&Kb[(size_t)(n0 + row) * HW + kk + col];
        __syncthreads();
        Vs[col + 0][row] = vv.x * av + dv; Vs[col + 1][row] = vv.y * av + dv;
        Vs[col + 2][row] = vv.z * av + dv; Vs[col + 3][row] = vv.w * av + dv;
        Ks[col + 0][row] = kv.x * ak + dk; Ks[col + 1][row] = kv.y * ak + dk;
        Ks[col + 2][row] = kv.z * ak + dk; Ks[col + 3][row] = kv.w * ak + dk;
        __syncthreads();
        #pragma unroll
        for (int k = 0; k < 16; k++) {
            float4 a4 = *(const float4*)&Vs[k][ty * 4];
            float4 b4 = *(const float4*)&Ks[k][tx * 4];
            float av2[4] = {a4.x, a4.y, a4.z, a4.w};
            float bv2[4] = {b4.x, b4.y, b4.z, b4.w};
            #pragma unroll
            for (int i = 0; i < 4; i++)
                #pragma unroll
                for (int j = 0; j < 4; j++)
                    acc[i][j] += av2[i] * bv2[j];
        }
    }

    float* Mp = &g_Mpart[s][(size_t)b * C * C];
    #pragma unroll
    for (int i = 0; i < 4; i++)
        #pragma unroll
        for (int j = 0; j < 4; j++)
            Mp[(size_t)(m0 + ty * 4 + i) * C + n0 + tx * 4 + j] = acc[i][j];
}

// ---------------------------------------------------------------------------
// K4: reduce split-K partials of M.  grid 512 x 256 = B*C*C/4 float4 lanes.
// ---------------------------------------------------------------------------
__global__ __launch_bounds__(256) void m_reduce()
{
    const int idx = blockIdx.x * 256 + threadIdx.x;   // float4 index
    float4 acc = make_float4(0.f, 0.f, 0.f, 0.f);
    #pragma unroll
    for (int s = 0; s < SPLIT; s++) {
        float4 v = ((const float4*)g_Mpart[s])[idx];
        acc.x += v.x; acc.y += v.y; acc.z += v.z; acc.w += v.w;
    }
    ((float4*)g_M)[idx] = acc;
}

// ---------------------------------------------------------------------------
// K5: out[b,c,q] = scale * sum_c' M[b,c,c'] * Qn[b,c',q]
// grid: (HW/64, C/64, B), block 256.
// ---------------------------------------------------------------------------
__global__ __launch_bounds__(256) void out_gemm(float* __restrict__ out)
{
    __shared__ float Ms[16][64];
    __shared__ float Qs[16][64];

    const int b = blockIdx.z;
    const float* Mb = &g_M[(size_t)b * C * C];
    const float* Qb = &g_Y[0][(size_t)b * C * HW];

    const int tid = threadIdx.x;
    const int n0 = blockIdx.x * 64;
    const int m0 = blockIdx.y * 64;
    const int tx = tid & 15, ty = tid >> 4;
    const int wrow = tid >> 2, wcol = (tid & 3) * 4;
    const int xrow = tid >> 4, xcol = (tid & 15) * 4;

    float acc[4][4] = {};

    for (int k0 = 0; k0 < C; k0 += 16) {
        float4 wv = *(const float4*)&Mb[(size_t)(m0 + wrow) * C + k0 + wcol];
        float aq = g_a[0][k0 + xrow], dq = g_d[0][k0 + xrow];
        float4 xv = *(const float4*)&Qb[(size_t)(k0 + xrow) * HW + n0 + xcol];
        __syncthreads();
        Ms[wcol + 0][wrow] = wv.x; Ms[wcol + 1][wrow] = wv.y;
        Ms[wcol + 2][wrow] = wv.z; Ms[wcol + 3][wrow] = wv.w;
        Qs[xrow][xcol + 0] = xv.x * aq + dq;
        Qs[xrow][xcol + 1] = xv.y * aq + dq;
        Qs[xrow][xcol + 2] = xv.z * aq + dq;
        Qs[xrow][xcol + 3] = xv.w * aq + dq;
        __syncthreads();
        #pragma unroll
        for (int k = 0; k < 16; k++) {
            float4 a4 = *(const float4*)&Ms[k][ty * 4];
            float4 b4 = *(const float4*)&Qs[k][tx * 4];
            float av2[4] = {a4.x, a4.y, a4.z, a4.w};
            float bv2[4] = {b4.x, b4.y, b4.z, b4.w};
            #pragma unroll
            for (int i = 0; i < 4; i++)
                #pragma unroll
                for (int j = 0; j < 4; j++)
                    acc[i][j] += av2[i] * bv2[j];
        }
    }

    const float scale = 0.125f;   // h^{-0.5}, h = 64
    #pragma unroll
    for (int i = 0; i < 4; i++)
        #pragma unroll
        for (int j = 0; j < 4; j++)
            out[((size_t)b * C + m0 + ty * 4 + i) * HW + n0 + tx * 4 + j] =
                scale * acc[i][j];
}

// ---------------------------------------------------------------------------
extern "C" void kernel_launch(void* const* d_in, const int* in_sizes, int n_in,
                              void* d_out, int out_size)
{
    const float* x     = (const float*)d_in[0];
    const float* Wq    = (const float*)d_in[1];
    const float* bq    = (const float*)d_in[2];
    const float* gq    = (const float*)d_in[3];
    const float* betaq = (const float*)d_in[4];
    const float* Wk    = (const float*)d_in[5];
    const float* bk    = (const float*)d_in[6];
    const float* gk    = (const float*)d_in[7];
    const float* betak = (const float*)d_in[8];
    const float* Wv    = (const float*)d_in[9];
    const float* bv    = (const float*)d_in[10];
    const float* gv    = (const float*)d_in[11];
    const float* betav = (const float*)d_in[12];
    float* out = (float*)d_out;

    proj_gemm<<<dim3(HW / 64, C / 64, 3 * B), 256>>>(x, Wq, bq, Wk, bk, Wv, bv);
    bn_stats<<<3 * C, 256>>>(gq, betaq, gk, betak, gv, betav);
    m_gemm<<<dim3(C / 64, C / 64, SPLIT * B), 256>>>();
    m_reduce<<<512, 256>>>();
    out_gemm<<<dim3(HW / 64, C / 64, B), 256>>>(out);
}

// round 2
// speedup vs baseline: 1.3119x; 1.3119x over previous
#include <cuda_runtime.h>
#include <cuda_bf16.h>
#include <cstdint>

#define B 8
#define C 256
#define HW 4096
#define BN_EPS 1e-5f
#define SPLIT 8
#define CHUNK (HW / SPLIT)   // 512
#define PAD 136
// swizzled smem index: conflict-free fragment reads + writes
#define SIDX(k2, mn) ((k2) * PAD + ((mn) ^ ((k2) >> 2)))

// ---- device scratch (no runtime allocation allowed) ----
__device__ uint32_t g_Yhi[3][(size_t)B * C * HW / 2];   // bf16 hi plane, packed pairs
__device__ uint32_t g_Ylo[3][(size_t)B * C * HW / 2];   // bf16 lo plane
__device__ float    g_a[3][C], g_d[3][C];               // BN affine
__device__ float    g_S[3][B * C];                      // per-(b,c) row sums
__device__ float    g_Gpart[SPLIT][(size_t)B * C * C];  // Gram split-K partials
__device__ uint32_t g_M2hi[(size_t)B * C * C / 2];      // folded M, bf16 planes
__device__ uint32_t g_M2lo[(size_t)B * C * C / 2];
__device__ float    g_r[B * C];                         // per-row additive term

// ---- helpers ----
__device__ __forceinline__ void split2(float e0, float e1, uint32_t& hi, uint32_t& lo) {
    __nv_bfloat16 h0 = __float2bfloat16(e0);
    __nv_bfloat16 h1 = __float2bfloat16(e1);
    __nv_bfloat162 hp = __halves2bfloat162(h0, h1);            // .x = e0 (low 16)
    __nv_bfloat162 lp = __floats2bfloat162_rn(e0 - __bfloat162float(h0),
                                              e1 - __bfloat162float(h1));
    hi = *reinterpret_cast<uint32_t*>(&hp);
    lo = *reinterpret_cast<uint32_t*>(&lp);
}

__device__ __forceinline__ void mma16816(float* c, const uint32_t* a, const uint32_t* b) {
    asm volatile(
        "mma.sync.aligned.m16n8k16.row.col.f32.bf16.bf16.f32 "
        "{%0,%1,%2,%3}, {%4,%5,%6,%7}, {%8,%9}, {%0,%1,%2,%3};\n"
        : "+f"(c[0]), "+f"(c[1]), "+f"(c[2]), "+f"(c[3])
        : "r"(a[0]), "r"(a[1]), "r"(a[2]), "r"(a[3]), "r"(b[0]), "r"(b[1]));
}

// 128x128 tile compute from staged hi/lo planes (BK=32 -> two k16 steps)
__device__ __forceinline__ void mma_compute(
    const uint32_t* __restrict__ Ah, const uint32_t* __restrict__ Al,
    const uint32_t* __restrict__ Bh, const uint32_t* __restrict__ Bl,
    float (*acc)[8][4], int lane, int wm, int wn)
{
    const int g = lane >> 2, tg = lane & 3;
#pragma unroll
    for (int s = 0; s < 2; s++) {
        const int k2a = s * 8 + tg, k2b = k2a + 4;
        uint32_t ah[2][4], al[2][4], bh[8][2], bl[8][2];
#pragma unroll
        for (int i = 0; i < 2; i++) {
            int mi = wm + i * 16 + g;
            ah[i][0] = Ah[SIDX(k2a, mi)];     ah[i][1] = Ah[SIDX(k2a, mi + 8)];
            ah[i][2] = Ah[SIDX(k2b, mi)];     ah[i][3] = Ah[SIDX(k2b, mi + 8)];
            al[i][0] = Al[SIDX(k2a, mi)];     al[i][1] = Al[SIDX(k2a, mi + 8)];
            al[i][2] = Al[SIDX(k2b, mi)];     al[i][3] = Al[SIDX(k2b, mi + 8)];
        }
#pragma unroll
        for (int j = 0; j < 8; j++) {
            int nj = wn + j * 8 + g;
            bh[j][0] = Bh[SIDX(k2a, nj)];     bh[j][1] = Bh[SIDX(k2b, nj)];
            bl[j][0] = Bl[SIDX(k2a, nj)];     bl[j][1] = Bl[SIDX(k2b, nj)];
        }
#pragma unroll
        for (int i = 0; i < 2; i++)
#pragma unroll
            for (int j = 0; j < 8; j++) {
                mma16816(acc[i][j], ah[i], bh[j]);
                mma16816(acc[i][j], ah[i], bl[j]);
                mma16816(acc[i][j], al[i], bh[j]);
            }
    }
}

// ---------------------------------------------------------------------------
// K1: projection GEMM  Y[p][b] = W_p[256x256] * x[b][256x4096] + bias
// fp32 inputs split to bf16 hi/lo at staging; output stored as bf16 planes.
// grid (32, 2, 24), block 256
// ---------------------------------------------------------------------------
__global__ __launch_bounds__(256, 1) void proj_gemm(
    const float* __restrict__ x,
    const float* __restrict__ Wq, const float* __restrict__ bq,
    const float* __restrict__ Wk, const float* __restrict__ bk,
    const float* __restrict__ Wv, const float* __restrict__ bv)
{
    __shared__ uint32_t As_hi[16 * PAD], As_lo[16 * PAD];
    __shared__ uint32_t Bs_hi[16 * PAD], Bs_lo[16 * PAD];

    const int p = blockIdx.z / B, b = blockIdx.z % B;
    const float* W    = (p == 0) ? Wq : (p == 1) ? Wk : Wv;
    const float* bias = (p == 0) ? bq : (p == 1) ? bk : bv;
    const float* xb = x + (size_t)b * C * HW;

    const int tid = threadIdx.x, lane = tid & 31, wid = tid >> 5;
    const int n0 = blockIdx.x * 128, m0 = blockIdx.y * 128;
    const int wm = (wid & 3) * 32, wn = (wid >> 2) * 64;

    float2 apre[8];
    float  bpre[8][2];
#pragma unroll
    for (int i = 0; i < 8; i++) {
        int idx = i * 256 + tid;
        int ak2 = idx & 15, am = idx >> 4;
        apre[i] = *(const float2*)&W[(size_t)(m0 + am) * C + 2 * ak2];
        int bk2 = idx >> 7, bn = idx & 127;
        const float* bp = &xb[(size_t)(2 * bk2) * HW + n0 + bn];
        bpre[i][0] = bp[0]; bpre[i][1] = bp[HW];
    }

    float acc[2][8][4] = {};
    for (int kt = 0; kt < 8; kt++) {
#pragma unroll
        for (int i = 0; i < 8; i++) {
            int idx = i * 256 + tid;
            int ak2 = idx & 15, am = idx >> 4;
            uint32_t hi, lo;
            split2(apre[i].x, apre[i].y, hi, lo);
            As_hi[SIDX(ak2, am)] = hi; As_lo[SIDX(ak2, am)] = lo;
            int bk2 = idx >> 7, bn = idx & 127;
            split2(bpre[i][0], bpre[i][1], hi, lo);
            Bs_hi[SIDX(bk2, bn)] = hi; Bs_lo[SIDX(bk2, bn)] = lo;
        }
        __syncthreads();
        if (kt < 7) {
            int k0 = (kt + 1) * 32;
#pragma unroll
            for (int i = 0; i < 8; i++) {
                int idx = i * 256 + tid;
                int ak2 = idx & 15, am = idx >> 4;
                apre[i] = *(const float2*)&W[(size_t)(m0 + am) * C + k0 + 2 * ak2];
                int bk2 = idx >> 7, bn = idx & 127;
                const float* bp = &xb[(size_t)(k0 + 2 * bk2) * HW + n0 + bn];
                bpre[i][0] = bp[0]; bpre[i][1] = bp[HW];
            }
        }
        mma_compute(As_hi, As_lo, Bs_hi, Bs_lo, acc, lane, wm, wn);
        __syncthreads();
    }

    // epilogue: +bias, split to bf16 hi/lo planes
    const int g = lane >> 2, tg = lane & 3;
#pragma unroll
    for (int i = 0; i < 2; i++)
#pragma unroll
        for (int j = 0; j < 8; j++) {
            int r0 = m0 + wm + i * 16 + g;
            int cc = n0 + wn + j * 8 + tg * 2;
            uint32_t hi, lo;
            float y0 = acc[i][j][0] + bias[r0], y1 = acc[i][j][1] + bias[r0];
            split2(y0, y1, hi, lo);
            size_t off = ((size_t)(b * C + r0) * HW + cc) >> 1;
            g_Yhi[p][off] = hi; g_Ylo[p][off] = lo;
            int r1 = r0 + 8;
            y0 = acc[i][j][2] + bias[r1]; y1 = acc[i][j][3] + bias[r1];
            split2(y0, y1, hi, lo);
            off = ((size_t)(b * C + r1) * HW + cc) >> 1;
            g_Yhi[p][off] = hi; g_Ylo[p][off] = lo;
        }
}

// ---------------------------------------------------------------------------
// K2: BN stats + per-(b,c) row sums.  grid 3*C, block 256.
// ---------------------------------------------------------------------------
__global__ __launch_bounds__(256) void bn_stats(
    const float* __restrict__ gq, const float* __restrict__ betaq,
    const float* __restrict__ gk, const float* __restrict__ betak,
    const float* __restrict__ gv, const float* __restrict__ betav)
{
    __shared__ float rs[256], rs2[256];
    const int p = blockIdx.x / C, c = blockIdx.x % C;
    const int tid = threadIdx.x;
    float tot_s = 0.f, tot_s2 = 0.f;

    for (int b = 0; b < B; b++) {
        const uint32_t* hi = &g_Yhi[p][((size_t)(b * C + c) * HW) >> 1];
        const uint32_t* lo = &g_Ylo[p][((size_t)(b * C + c) * HW) >> 1];
        float s = 0.f, s2 = 0.f;
        for (int i = tid; i < HW / 2; i += 256) {
            uint32_t h = hi[i], l = lo[i];
            __nv_bfloat162 hb = *reinterpret_cast<__nv_bfloat162*>(&h);
            __nv_bfloat162 lb = *reinterpret_cast<__nv_bfloat162*>(&l);
            float y0 = __bfloat162float(hb.x) + __bfloat162float(lb.x);
            float y1 = __bfloat162float(hb.y) + __bfloat162float(lb.y);
            s += y0 + y1; s2 += y0 * y0 + y1 * y1;
        }
        rs[tid] = s; rs2[tid] = s2;
        __syncthreads();
        for (int off = 128; off > 0; off >>= 1) {
            if (tid < off) { rs[tid] += rs[tid + off]; rs2[tid] += rs2[tid + off]; }
            __syncthreads();
        }
        if (tid == 0) {
            g_S[p][b * C + c] = rs[0];
            tot_s += rs[0]; tot_s2 += rs2[0];
        }
        __syncthreads();
    }
    if (tid == 0) {
        const float inv_n = 1.f / (float)(B * HW);
        float mu  = tot_s * inv_n;
        float var = tot_s2 * inv_n - mu * mu;
        float inv = rsqrtf(var + BN_EPS);
        const float* gg = (p == 0) ? gq : (p == 1) ? gk : gv;
        const float* be = (p == 0) ? betaq : (p == 1) ? betak : betav;
        float a = gg[c] * inv;
        g_a[p][c] = a;
        g_d[p][c] = be[c] - mu * a;
    }
}

// ---------------------------------------------------------------------------
// K3: Gram GEMM  G[b] = Vraw * Kraw^T  (bf16 planes, split-K = 8)
// grid (2, 2, 64), block 256
// ---------------------------------------------------------------------------
__global__ __launch_bounds__(256, 1) void gram_gemm()
{
    __shared__ uint32_t As_hi[16 * PAD], As_lo[16 * PAD];
    __shared__ uint32_t Bs_hi[16 * PAD], Bs_lo[16 * PAD];

    const int s = blockIdx.z / B, b = blockIdx.z % B;
    const int m0 = blockIdx.y * 128, n0 = blockIdx.x * 128;
    const int tid = threadIdx.x, lane = tid & 31, wid = tid >> 5;
    const int wm = (wid & 3) * 32, wn = (wid >> 2) * 64;
    const size_t rstride = HW / 2;
    const size_t base = (size_t)b * C * rstride;
    const int kb32 = (s * CHUNK) >> 1;

    uint32_t pah[8], pal[8], pbh[8], pbl[8];
#pragma unroll
    for (int i = 0; i < 8; i++) {
        int idx = i * 256 + tid;
        int k2 = idx & 15, mn = idx >> 4;
        size_t offA = base + (size_t)(m0 + mn) * rstride + kb32 + k2;
        pah[i] = g_Yhi[2][offA]; pal[i] = g_Ylo[2][offA];
        size_t offB = base + (size_t)(n0 + mn) * rstride + kb32 + k2;
        pbh[i] = g_Yhi[1][offB]; pbl[i] = g_Ylo[1][offB];
    }

    float acc[2][8][4] = {};
    for (int kt = 0; kt < CHUNK / 32; kt++) {
#pragma unroll
        for (int i = 0; i < 8; i++) {
            int idx = i * 256 + tid;
            int k2 = idx & 15, mn = idx >> 4;
            As_hi[SIDX(k2, mn)] = pah[i]; As_lo[SIDX(k2, mn)] = pal[i];
            Bs_hi[SIDX(k2, mn)] = pbh[i]; Bs_lo[SIDX(k2, mn)] = pbl[i];
        }
        __syncthreads();
        if (kt < CHUNK / 32 - 1) {
            int ko = kb32 + (kt + 1) * 16;
#pragma unroll
            for (int i = 0; i < 8; i++) {
                int idx = i * 256 + tid;
                int k2 = idx & 15, mn = idx >> 4;
                size_t offA = base + (size_t)(m0 + mn) * rstride + ko + k2;
                pah[i] = g_Yhi[2][offA]; pal[i] = g_Ylo[2][offA];
                size_t offB = base + (size_t)(n0 + mn) * rstride + ko + k2;
                pbh[i] = g_Yhi[1][offB]; pbl[i] = g_Ylo[1][offB];
            }
        }
        mma_compute(As_hi, As_lo, Bs_hi, Bs_lo, acc, lane, wm, wn);
        __syncthreads();
    }

    float* Gp = &g_Gpart[s][(size_t)b * C * C];
    const int g = lane >> 2, tg = lane & 3;
#pragma unroll
    for (int i = 0; i < 2; i++)
#pragma unroll
        for (int j = 0; j < 8; j++) {
            int r0 = m0 + wm + i * 16 + g;
            int cc = n0 + wn + j * 8 + tg * 2;
            *(float2*)&Gp[(size_t)r0 * C + cc] = make_float2(acc[i][j][0], acc[i][j][1]);
            *(float2*)&Gp[(size_t)(r0 + 8) * C + cc] = make_float2(acc[i][j][2], acc[i][j][3]);
        }
}

// ---------------------------------------------------------------------------
// K4: reduce Gram partials + apply all BN affines + scale; fold aq into M,
// produce r[c] = scale * sum_c' M[c,c'] dq[c'].  grid B, block 256.
// ---------------------------------------------------------------------------
__global__ __launch_bounds__(256) void m_fix()
{
    const int b = blockIdx.x;
    const int wid = threadIdx.x >> 5, lane = threadIdx.x & 31;
    __nv_bfloat16* M2h = reinterpret_cast<__nv_bfloat16*>(g_M2hi);
    __nv_bfloat16* M2l = reinterpret_cast<__nv_bfloat16*>(g_M2lo);

    for (int m = wid; m < C; m += 8) {
        const float av = g_a[2][m], dv = g_d[2][m];
        const float SV = g_S[2][b * C + m];
        float rsum = 0.f;
#pragma unroll
        for (int j = 0; j < 8; j++) {
            int c = lane + j * 32;
            float e = 0.f;
#pragma unroll
            for (int s = 0; s < SPLIT; s++)
                e += g_Gpart[s][(size_t)b * C * C + (size_t)m * C + c];
            float ak = g_a[1][c], dk = g_d[1][c];
            float SK = g_S[1][b * C + c];
            float M = av * ak * e + av * dk * SV + dv * ak * SK + 4096.f * dv * dk;
            float M2 = 0.125f * M * g_a[0][c];
            rsum += M * g_d[0][c];
            __nv_bfloat16 hi = __float2bfloat16(M2);
            __nv_bfloat16 lo = __float2bfloat16(M2 - __bfloat162float(hi));
            size_t off = (size_t)(b * C + m) * C + c;
            M2h[off] = hi; M2l[off] = lo;
        }
        rsum *= 0.125f;
#pragma unroll
        for (int o = 16; o > 0; o >>= 1)
            rsum += __shfl_xor_sync(0xffffffffu, rsum, o);
        if (lane == 0) g_r[b * C + m] = rsum;
    }
}

// ---------------------------------------------------------------------------
// K5: out[b] = M2[b] * Qraw[b] + r[b]   grid (32, 2, 8), block 256
// ---------------------------------------------------------------------------
__global__ __launch_bounds__(256, 1) void out_gemm(float* __restrict__ out)
{
    __shared__ uint32_t As_hi[16 * PAD], As_lo[16 * PAD];
    __shared__ uint32_t Bs_hi[16 * PAD], Bs_lo[16 * PAD];

    const int b = blockIdx.z;
    const int n0 = blockIdx.x * 128, m0 = blockIdx.y * 128;
    const int tid = threadIdx.x, lane = tid & 31, wid = tid >> 5;
    const int wm = (wid & 3) * 32, wn = (wid >> 2) * 64;

    const __nv_bfloat16* Qh = reinterpret_cast<const __nv_bfloat16*>(g_Yhi[0])
                              + (size_t)b * C * HW;
    const __nv_bfloat16* Ql = reinterpret_cast<const __nv_bfloat16*>(g_Ylo[0])
                              + (size_t)b * C * HW;
    const size_t mbase = (size_t)(b * C + m0) * (C / 2);

    uint32_t pah[8], pal[8];
    __nv_bfloat16 qh[8][2], ql[8][2];
#pragma unroll
    for (int i = 0; i < 8; i++) {
        int idx = i * 256 + tid;
        int ak2 = idx & 15, am = idx >> 4;
        size_t offA = mbase + (size_t)am * (C / 2) + ak2;
        pah[i] = g_M2hi[offA]; pal[i] = g_M2lo[offA];
        int bk2 = idx >> 7, bn = idx & 127;
        size_t q0 = (size_t)(2 * bk2) * HW + n0 + bn;
        qh[i][0] = Qh[q0]; qh[i][1] = Qh[q0 + HW];
        ql[i][0] = Ql[q0]; ql[i][1] = Ql[q0 + HW];
    }

    float acc[2][8][4] = {};
    for (int kt = 0; kt < 8; kt++) {
#pragma unroll
        for (int i = 0; i < 8; i++) {
            int idx = i * 256 + tid;
            int ak2 = idx & 15, am = idx >> 4;
            As_hi[SIDX(ak2, am)] = pah[i]; As_lo[SIDX(ak2, am)] = pal[i];
            int bk2 = idx >> 7, bn = idx & 127;
            __nv_bfloat162 hp = __halves2bfloat162(qh[i][0], qh[i][1]);
            __nv_bfloat162 lp = __halves2bfloat162(ql[i][0], ql[i][1]);
            Bs_hi[SIDX(bk2, bn)] = *reinterpret_cast<uint32_t*>(&hp);
            Bs_lo[SIDX(bk2, bn)] = *reinterpret_cast<uint32_t*>(&lp);
        }
        __syncthreads();
        if (kt < 7) {
            int k0 = (kt + 1) * 32;
#pragma unroll
            for (int i = 0; i < 8; i++) {
                int idx = i * 256 + tid;
                int ak2 = idx & 15, am = idx >> 4;
                size_t offA = mbase + (size_t)am * (C / 2) + (k0 >> 1) + ak2;
                pah[i] = g_M2hi[offA]; pal[i] = g_M2lo[offA];
                int bk2 = idx >> 7, bn = idx & 127;
                size_t q0 = (size_t)(k0 + 2 * bk2) * HW + n0 + bn;
                qh[i][0] = Qh[q0]; qh[i][1] = Qh[q0 + HW];
                ql[i][0] = Ql[q0]; ql[i][1] = Ql[q0 + HW];
            }
        }
        mma_compute(As_hi, As_lo, Bs_hi, Bs_lo, acc, lane, wm, wn);
        __syncthreads();
    }

    const int g = lane >> 2, tg = lane & 3;
#pragma unroll
    for (int i = 0; i < 2; i++)
#pragma unroll
        for (int j = 0; j < 8; j++) {
            int r0 = m0 + wm + i * 16 + g;
            int cc = n0 + wn + j * 8 + tg * 2;
            float rr = g_r[b * C + r0];
            *(float2*)&out[(size_t)(b * C + r0) * HW + cc] =
                make_float2(acc[i][j][0] + rr, acc[i][j][1] + rr);
            rr = g_r[b * C + r0 + 8];
            *(float2*)&out[(size_t)(b * C + r0 + 8) * HW + cc] =
                make_float2(acc[i][j][2] + rr, acc[i][j][3] + rr);
        }
}

// ---------------------------------------------------------------------------
extern "C" void kernel_launch(void* const* d_in, const int* in_sizes, int n_in,
                              void* d_out, int out_size)
{
    const float* x     = (const float*)d_in[0];
    const float* Wq    = (const float*)d_in[1];
    const float* bq    = (const float*)d_in[2];
    const float* gq    = (const float*)d_in[3];
    const float* betaq = (const float*)d_in[4];
    const float* Wk    = (const float*)d_in[5];
    const float* bk    = (const float*)d_in[6];
    const float* gk    = (const float*)d_in[7];
    const float* betak = (const float*)d_in[8];
    const float* Wv    = (const float*)d_in[9];
    const float* bv    = (const float*)d_in[10];
    const float* gv    = (const float*)d_in[11];
    const float* betav = (const float*)d_in[12];
    float* out = (float*)d_out;

    proj_gemm<<<dim3(32, 2, 3 * B), 256>>>(x, Wq, bq, Wk, bk, Wv, bv);
    bn_stats<<<3 * C, 256>>>(gq, betaq, gk, betak, gv, betav);
    gram_gemm<<<dim3(2, 2, SPLIT * B), 256>>>();
    m_fix<<<B, 256>>>();
    out_gemm<<<dim3(32, 2, B), 256>>>(out);
}

// round 3
// speedup vs baseline: 2.0023x; 1.5262x over previous
#include <cuda_runtime.h>
#include <cuda_bf16.h>
#include <cstdint>

#define B 8
#define C 256
#define HW 4096
#define BN_EPS 1e-5f
#define SPLIT 16
#define CHUNK (HW / SPLIT)   // 256
#define PAD 136
#define NT 32                // n-tiles in proj (HW/128)
// swizzled smem index: conflict-free fragment reads + writes
#define SIDX(k2, mn) ((k2) * PAD + ((mn) ^ ((k2) >> 2)))

// ---- device scratch (no runtime allocation allowed) ----
__device__ uint32_t g_Yhi[3][(size_t)B * C * HW / 2];   // bf16 hi plane, packed pairs
__device__ uint32_t g_Ylo[3][(size_t)B * C * HW / 2];   // bf16 lo plane
__device__ float    g_a[3][C], g_d[3][C];               // BN affine
__device__ float    g_S[3][B * C];                      // per-(b,c) row sums
__device__ float    g_Psum[3][(size_t)B * NT * C];      // proj partial sums
__device__ float    g_Psum2[3][(size_t)B * NT * C];     // proj partial sumsq
__device__ float    g_Gpart[SPLIT][(size_t)B * C * C];  // Gram split-K partials
__device__ uint32_t g_M2hi[(size_t)B * C * C / 2];      // folded M, bf16 planes
__device__ uint32_t g_M2lo[(size_t)B * C * C / 2];
__device__ float    g_r[B * C];                         // per-row additive term

// ---- helpers ----
__device__ __forceinline__ void split2(float e0, float e1, uint32_t& hi, uint32_t& lo) {
    __nv_bfloat16 h0 = __float2bfloat16(e0);
    __nv_bfloat16 h1 = __float2bfloat16(e1);
    __nv_bfloat162 hp = __halves2bfloat162(h0, h1);            // .x = e0 (low 16)
    __nv_bfloat162 lp = __floats2bfloat162_rn(e0 - __bfloat162float(h0),
                                              e1 - __bfloat162float(h1));
    hi = *reinterpret_cast<uint32_t*>(&hp);
    lo = *reinterpret_cast<uint32_t*>(&lp);
}

__device__ __forceinline__ void mma16816(float* c, const uint32_t* a, const uint32_t* b) {
    asm volatile(
        "mma.sync.aligned.m16n8k16.row.col.f32.bf16.bf16.f32 "
        "{%0,%1,%2,%3}, {%4,%5,%6,%7}, {%8,%9}, {%0,%1,%2,%3};\n"
        : "+f"(c[0]), "+f"(c[1]), "+f"(c[2]), "+f"(c[3])
        : "r"(a[0]), "r"(a[1]), "r"(a[2]), "r"(a[3]), "r"(b[0]), "r"(b[1]));
}

// 128x128 tile compute from staged hi/lo planes (BK=32 -> two k16 steps)
__device__ __forceinline__ void mma_compute(
    const uint32_t* __restrict__ Ah, const uint32_t* __restrict__ Al,
    const uint32_t* __restrict__ Bh, const uint32_t* __restrict__ Bl,
    float (*acc)[8][4], int lane, int wm, int wn)
{
    const int g = lane >> 2, tg = lane & 3;
#pragma unroll
    for (int s = 0; s < 2; s++) {
        const int k2a = s * 8 + tg, k2b = k2a + 4;
        uint32_t ah[2][4], al[2][4], bh[8][2], bl[8][2];
#pragma unroll
        for (int i = 0; i < 2; i++) {
            int mi = wm + i * 16 + g;
            ah[i][0] = Ah[SIDX(k2a, mi)];     ah[i][1] = Ah[SIDX(k2a, mi + 8)];
            ah[i][2] = Ah[SIDX(k2b, mi)];     ah[i][3] = Ah[SIDX(k2b, mi + 8)];
            al[i][0] = Al[SIDX(k2a, mi)];     al[i][1] = Al[SIDX(k2a, mi + 8)];
            al[i][2] = Al[SIDX(k2b, mi)];     al[i][3] = Al[SIDX(k2b, mi + 8)];
        }
#pragma unroll
        for (int j = 0; j < 8; j++) {
            int nj = wn + j * 8 + g;
            bh[j][0] = Bh[SIDX(k2a, nj)];     bh[j][1] = Bh[SIDX(k2b, nj)];
            bl[j][0] = Bl[SIDX(k2a, nj)];     bl[j][1] = Bl[SIDX(k2b, nj)];
        }
#pragma unroll
        for (int i = 0; i < 2; i++)
#pragma unroll
            for (int j = 0; j < 8; j++) {
                mma16816(acc[i][j], ah[i], bh[j]);
                mma16816(acc[i][j], ah[i], bl[j]);
                mma16816(acc[i][j], al[i], bh[j]);
            }
    }
}

// ---------------------------------------------------------------------------
// K1: projection GEMM  Y[p][b] = W_p[256x256] * x[b][256x4096] + bias
// Also emits per-(row, n-tile) partial sums / sumsq from fp32 accumulators.
// grid (32, 2, 24), block 256
// ---------------------------------------------------------------------------
__global__ __launch_bounds__(256, 1) void proj_gemm(
    const float* __restrict__ x,
    const float* __restrict__ Wq, const float* __restrict__ bq,
    const float* __restrict__ Wk, const float* __restrict__ bk,
    const float* __restrict__ Wv, const float* __restrict__ bv)
{
    __shared__ uint32_t As_hi[16 * PAD], As_lo[16 * PAD];
    __shared__ uint32_t Bs_hi[16 * PAD], Bs_lo[16 * PAD];

    const int p = blockIdx.z / B, b = blockIdx.z % B;
    const float* W    = (p == 0) ? Wq : (p == 1) ? Wk : Wv;
    const float* bias = (p == 0) ? bq : (p == 1) ? bk : bv;
    const float* xb = x + (size_t)b * C * HW;

    const int tid = threadIdx.x, lane = tid & 31, wid = tid >> 5;
    const int n0 = blockIdx.x * 128, m0 = blockIdx.y * 128;
    const int wm = (wid & 3) * 32, wn = (wid >> 2) * 64;

    float2 apre[8];
    float  bpre[8][2];
#pragma unroll
    for (int i = 0; i < 8; i++) {
        int idx = i * 256 + tid;
        int ak2 = idx & 15, am = idx >> 4;
        apre[i] = *(const float2*)&W[(size_t)(m0 + am) * C + 2 * ak2];
        int bk2 = idx >> 7, bn = idx & 127;
        const float* bp = &xb[(size_t)(2 * bk2) * HW + n0 + bn];
        bpre[i][0] = bp[0]; bpre[i][1] = bp[HW];
    }

    float acc[2][8][4] = {};
    for (int kt = 0; kt < 8; kt++) {
#pragma unroll
        for (int i = 0; i < 8; i++) {
            int idx = i * 256 + tid;
            int ak2 = idx & 15, am = idx >> 4;
            uint32_t hi, lo;
            split2(apre[i].x, apre[i].y, hi, lo);
            As_hi[SIDX(ak2, am)] = hi; As_lo[SIDX(ak2, am)] = lo;
            int bk2 = idx >> 7, bn = idx & 127;
            split2(bpre[i][0], bpre[i][1], hi, lo);
            Bs_hi[SIDX(bk2, bn)] = hi; Bs_lo[SIDX(bk2, bn)] = lo;
        }
        __syncthreads();
        if (kt < 7) {
            int k0 = (kt + 1) * 32;
#pragma unroll
            for (int i = 0; i < 8; i++) {
                int idx = i * 256 + tid;
                int ak2 = idx & 15, am = idx >> 4;
                apre[i] = *(const float2*)&W[(size_t)(m0 + am) * C + k0 + 2 * ak2];
                int bk2 = idx >> 7, bn = idx & 127;
                const float* bp = &xb[(size_t)(k0 + 2 * bk2) * HW + n0 + bn];
                bpre[i][0] = bp[0]; bpre[i][1] = bp[HW];
            }
        }
        mma_compute(As_hi, As_lo, Bs_hi, Bs_lo, acc, lane, wm, wn);
        __syncthreads();
    }

    // epilogue: +bias, split to bf16 planes, and per-row partial stats
    const int g = lane >> 2, tg = lane & 3;
    float rsum[4] = {}, rsum2[4] = {};
#pragma unroll
    for (int i = 0; i < 2; i++)
#pragma unroll
        for (int j = 0; j < 8; j++) {
            int r0 = m0 + wm + i * 16 + g;
            int cc = n0 + wn + j * 8 + tg * 2;
            uint32_t hi, lo;
            float y0 = acc[i][j][0] + bias[r0], y1 = acc[i][j][1] + bias[r0];
            rsum[i * 2]  += y0 + y1;
            rsum2[i * 2] += y0 * y0 + y1 * y1;
            split2(y0, y1, hi, lo);
            size_t off = ((size_t)(b * C + r0) * HW + cc) >> 1;
            g_Yhi[p][off] = hi; g_Ylo[p][off] = lo;
            int r1 = r0 + 8;
            y0 = acc[i][j][2] + bias[r1]; y1 = acc[i][j][3] + bias[r1];
            rsum[i * 2 + 1]  += y0 + y1;
            rsum2[i * 2 + 1] += y0 * y0 + y1 * y1;
            split2(y0, y1, hi, lo);
            off = ((size_t)(b * C + r1) * HW + cc) >> 1;
            g_Yhi[p][off] = hi; g_Ylo[p][off] = lo;
        }
    // reduce across the 4 lanes sharing each row (tg bits)
#pragma unroll
    for (int q = 0; q < 4; q++) {
        rsum[q]  += __shfl_xor_sync(0xffffffffu, rsum[q], 1);
        rsum[q]  += __shfl_xor_sync(0xffffffffu, rsum[q], 2);
        rsum2[q] += __shfl_xor_sync(0xffffffffu, rsum2[q], 1);
        rsum2[q] += __shfl_xor_sync(0xffffffffu, rsum2[q], 2);
    }
    __syncthreads();
    float* sb  = reinterpret_cast<float*>(As_hi);   // [128][2]
    float* sb2 = reinterpret_cast<float*>(Bs_hi);   // [128][2]
    if (tg == 0) {
        const int half = wn >> 6;
#pragma unroll
        for (int q = 0; q < 4; q++) {
            int r = wm + (q >> 1) * 16 + (q & 1) * 8 + g;   // local row
            sb[r * 2 + half]  = rsum[q];
            sb2[r * 2 + half] = rsum2[q];
        }
    }
    __syncthreads();
    if (tid < 128) {
        size_t off = ((size_t)b * NT + blockIdx.x) * C + m0 + tid;
        g_Psum[p][off]  = sb[tid * 2] + sb[tid * 2 + 1];
        g_Psum2[p][off] = sb2[tid * 2] + sb2[tid * 2 + 1];
    }
}

// ---------------------------------------------------------------------------
// K2: reduce proj partial stats -> BN affine + per-(b,c) sums.
// grid 3*C, block 256 (warp w = batch b, lane = n-tile).
// ---------------------------------------------------------------------------
__global__ __launch_bounds__(256) void bn_stats(
    const float* __restrict__ gq, const float* __restrict__ betaq,
    const float* __restrict__ gk, const float* __restrict__ betak,
    const float* __restrict__ gv, const float* __restrict__ betav)
{
    __shared__ float bs[8], bs2[8];
    const int p = blockIdx.x / C, c = blockIdx.x % C;
    const int lane = threadIdx.x & 31, b = threadIdx.x >> 5;

    size_t off = ((size_t)b * NT + lane) * C + c;
    float s  = g_Psum[p][off];
    float s2 = g_Psum2[p][off];
#pragma unroll
    for (int o = 16; o > 0; o >>= 1) {
        s  += __shfl_xor_sync(0xffffffffu, s, o);
        s2 += __shfl_xor_sync(0xffffffffu, s2, o);
    }
    if (lane == 0) {
        g_S[p][b * C + c] = s;
        bs[b] = s; bs2[b] = s2;
    }
    __syncthreads();
    if (threadIdx.x == 0) {
        float ts = 0.f, ts2 = 0.f;
#pragma unroll
        for (int i = 0; i < 8; i++) { ts += bs[i]; ts2 += bs2[i]; }
        const float inv_n = 1.f / (float)(B * HW);
        float mu  = ts * inv_n;
        float var = ts2 * inv_n - mu * mu;
        float inv = rsqrtf(var + BN_EPS);
        const float* gg = (p == 0) ? gq : (p == 1) ? gk : gv;
        const float* be = (p == 0) ? betaq : (p == 1) ? betak : betav;
        float a = gg[c] * inv;
        g_a[p][c] = a;
        g_d[p][c] = be[c] - mu * a;
    }
}

// ---------------------------------------------------------------------------
// K3: Gram GEMM  G[b] = Vraw * Kraw^T  (bf16 planes, split-K = 16)
// grid (2, 2, SPLIT*B), block 256
// ---------------------------------------------------------------------------
__global__ __launch_bounds__(256, 1) void gram_gemm()
{
    __shared__ uint32_t As_hi[16 * PAD], As_lo[16 * PAD];
    __shared__ uint32_t Bs_hi[16 * PAD], Bs_lo[16 * PAD];

    const int s = blockIdx.z / B, b = blockIdx.z % B;
    const int m0 = blockIdx.y * 128, n0 = blockIdx.x * 128;
    const int tid = threadIdx.x, lane = tid & 31, wid = tid >> 5;
    const int wm = (wid & 3) * 32, wn = (wid >> 2) * 64;
    const size_t rstride = HW / 2;
    const size_t base = (size_t)b * C * rstride;
    const int kb32 = (s * CHUNK) >> 1;

    uint32_t pah[8], pal[8], pbh[8], pbl[8];
#pragma unroll
    for (int i = 0; i < 8; i++) {
        int idx = i * 256 + tid;
        int k2 = idx & 15, mn = idx >> 4;
        size_t offA = base + (size_t)(m0 + mn) * rstride + kb32 + k2;
        pah[i] = g_Yhi[2][offA]; pal[i] = g_Ylo[2][offA];
        size_t offB = base + (size_t)(n0 + mn) * rstride + kb32 + k2;
        pbh[i] = g_Yhi[1][offB]; pbl[i] = g_Ylo[1][offB];
    }

    float acc[2][8][4] = {};
    for (int kt = 0; kt < CHUNK / 32; kt++) {
#pragma unroll
        for (int i = 0; i < 8; i++) {
            int idx = i * 256 + tid;
            int k2 = idx & 15, mn = idx >> 4;
            As_hi[SIDX(k2, mn)] = pah[i]; As_lo[SIDX(k2, mn)] = pal[i];
            Bs_hi[SIDX(k2, mn)] = pbh[i]; Bs_lo[SIDX(k2, mn)] = pbl[i];
        }
        __syncthreads();
        if (kt < CHUNK / 32 - 1) {
            int ko = kb32 + (kt + 1) * 16;
#pragma unroll
            for (int i = 0; i < 8; i++) {
                int idx = i * 256 + tid;
                int k2 = idx & 15, mn = idx >> 4;
                size_t offA = base + (size_t)(m0 + mn) * rstride + ko + k2;
                pah[i] = g_Yhi[2][offA]; pal[i] = g_Ylo[2][offA];
                size_t offB = base + (size_t)(n0 + mn) * rstride + ko + k2;
                pbh[i] = g_Yhi[1][offB]; pbl[i] = g_Ylo[1][offB];
            }
        }
        mma_compute(As_hi, As_lo, Bs_hi, Bs_lo, acc, lane, wm, wn);
        __syncthreads();
    }

    float* Gp = &g_Gpart[s][(size_t)b * C * C];
    const int g = lane >> 2, tg = lane & 3;
#pragma unroll
    for (int i = 0; i < 2; i++)
#pragma unroll
        for (int j = 0; j < 8; j++) {
            int r0 = m0 + wm + i * 16 + g;
            int cc = n0 + wn + j * 8 + tg * 2;
            *(float2*)&Gp[(size_t)r0 * C + cc] = make_float2(acc[i][j][0], acc[i][j][1]);
            *(float2*)&Gp[(size_t)(r0 + 8) * C + cc] = make_float2(acc[i][j][2], acc[i][j][3]);
        }
}

// ---------------------------------------------------------------------------
// K4: reduce Gram partials + apply all BN affines + scale; fold aq into M,
// produce r.  grid (C rows, B), block 256 (one c per thread).
// ---------------------------------------------------------------------------
__global__ __launch_bounds__(256) void m_fix()
{
    __shared__ float red[256];
    const int m = blockIdx.x, b = blockIdx.y;
    const int c = threadIdx.x;
    __nv_bfloat16* M2h = reinterpret_cast<__nv_bfloat16*>(g_M2hi);
    __nv_bfloat16* M2l = reinterpret_cast<__nv_bfloat16*>(g_M2lo);

    const float av = g_a[2][m], dv = g_d[2][m];
    const float SV = g_S[2][b * C + m];

    const size_t row = (size_t)b * C * C + (size_t)m * C + c;
    float e = 0.f;
#pragma unroll
    for (int s = 0; s < SPLIT; s++)
        e += g_Gpart[s][row];

    float ak = g_a[1][c], dk = g_d[1][c];
    float SK = g_S[1][b * C + c];
    float M = av * ak * e + av * dk * SV + dv * ak * SK + 4096.f * dv * dk;
    float M2 = 0.125f * M * g_a[0][c];
    __nv_bfloat16 hi = __float2bfloat16(M2);
    __nv_bfloat16 lo = __float2bfloat16(M2 - __bfloat162float(hi));
    size_t off = (size_t)(b * C + m) * C + c;
    M2h[off] = hi; M2l[off] = lo;

    red[c] = M * g_d[0][c];
    __syncthreads();
    for (int o = 128; o > 0; o >>= 1) {
        if (c < o) red[c] += red[c + o];
        __syncthreads();
    }
    if (c == 0) g_r[b * C + m] = 0.125f * red[0];
}

// ---------------------------------------------------------------------------
// K5: out[b] = M2[b] * Qraw[b] + r[b]   grid (32, 2, 8), block 256
// ---------------------------------------------------------------------------
__global__ __launch_bounds__(256, 1) void out_gemm(float* __restrict__ out)
{
    __shared__ uint32_t As_hi[16 * PAD], As_lo[16 * PAD];
    __shared__ uint32_t Bs_hi[16 * PAD], Bs_lo[16 * PAD];

    const int b = blockIdx.z;
    const int n0 = blockIdx.x * 128, m0 = blockIdx.y * 128;
    const int tid = threadIdx.x, lane = tid & 31, wid = tid >> 5;
    const int wm = (wid & 3) * 32, wn = (wid >> 2) * 64;

    const __nv_bfloat16* Qh = reinterpret_cast<const __nv_bfloat16*>(g_Yhi[0])
                              + (size_t)b * C * HW;
    const __nv_bfloat16* Ql = reinterpret_cast<const __nv_bfloat16*>(g_Ylo[0])
                              + (size_t)b * C * HW;
    const size_t mbase = (size_t)(b * C + m0) * (C / 2);

    uint32_t pah[8], pal[8];
    __nv_bfloat16 qh[8][2], ql[8][2];
#pragma unroll
    for (int i = 0; i < 8; i++) {
        int idx = i * 256 + tid;
        int ak2 = idx & 15, am = idx >> 4;
        size_t offA = mbase + (size_t)am * (C / 2) + ak2;
        pah[i] = g_M2hi[offA]; pal[i] = g_M2lo[offA];
        int bk2 = idx >> 7, bn = idx & 127;
        size_t q0 = (size_t)(2 * bk2) * HW + n0 + bn;
        qh[i][0] = Qh[q0]; qh[i][1] = Qh[q0 + HW];
        ql[i][0] = Ql[q0]; ql[i][1] = Ql[q0 + HW];
    }

    float acc[2][8][4] = {};
    for (int kt = 0; kt < 8; kt++) {
#pragma unroll
        for (int i = 0; i < 8; i++) {
            int idx = i * 256 + tid;
            int ak2 = idx & 15, am = idx >> 4;
            As_hi[SIDX(ak2, am)] = pah[i]; As_lo[SIDX(ak2, am)] = pal[i];
            int bk2 = idx >> 7, bn = idx & 127;
            __nv_bfloat162 hp = __halves2bfloat162(qh[i][0], qh[i][1]);
            __nv_bfloat162 lp = __halves2bfloat162(ql[i][0], ql[i][1]);
            Bs_hi[SIDX(bk2, bn)] = *reinterpret_cast<uint32_t*>(&hp);
            Bs_lo[SIDX(bk2, bn)] = *reinterpret_cast<uint32_t*>(&lp);
        }
        __syncthreads();
        if (kt < 7) {
            int k0 = (kt + 1) * 32;
#pragma unroll
            for (int i = 0; i < 8; i++) {
                int idx = i * 256 + tid;
                int ak2 = idx & 15, am = idx >> 4;
                size_t offA = mbase + (size_t)am * (C / 2) + (k0 >> 1) + ak2;
                pah[i] = g_M2hi[offA]; pal[i] = g_M2lo[offA];
                int bk2 = idx >> 7, bn = idx & 127;
                size_t q0 = (size_t)(k0 + 2 * bk2) * HW + n0 + bn;
                qh[i][0] = Qh[q0]; qh[i][1] = Qh[q0 + HW];
                ql[i][0] = Ql[q0]; ql[i][1] = Ql[q0 + HW];
            }
        }
        mma_compute(As_hi, As_lo, Bs_hi, Bs_lo, acc, lane, wm, wn);
        __syncthreads();
    }

    const int g = lane >> 2, tg = lane & 3;
#pragma unroll
    for (int i = 0; i < 2; i++)
#pragma unroll
        for (int j = 0; j < 8; j++) {
            int r0 = m0 + wm + i * 16 + g;
            int cc = n0 + wn + j * 8 + tg * 2;
            float rr = g_r[b * C + r0];
            *(float2*)&out[(size_t)(b * C + r0) * HW + cc] =
                make_float2(acc[i][j][0] + rr, acc[i][j][1] + rr);
            rr = g_r[b * C + r0 + 8];
            *(float2*)&out[(size_t)(b * C + r0 + 8) * HW + cc] =
                make_float2(acc[i][j][2] + rr, acc[i][j][3] + rr);
        }
}

// ---------------------------------------------------------------------------
extern "C" void kernel_launch(void* const* d_in, const int* in_sizes, int n_in,
                              void* d_out, int out_size)
{
    const float* x     = (const float*)d_in[0];
    const float* Wq    = (const float*)d_in[1];
    const float* bq    = (const float*)d_in[2];
    const float* gq    = (const float*)d_in[3];
    const float* betaq = (const float*)d_in[4];
    const float* Wk    = (const float*)d_in[5];
    const float* bk    = (const float*)d_in[6];
    const float* gk    = (const float*)d_in[7];
    const float* betak = (const float*)d_in[8];
    const float* Wv    = (const float*)d_in[9];
    const float* bv    = (const float*)d_in[10];
    const float* gv    = (const float*)d_in[11];
    const float* betav = (const float*)d_in[12];
    float* out = (float*)d_out;

    proj_gemm<<<dim3(32, 2, 3 * B), 256>>>(x, Wq, bq, Wk, bk, Wv, bv);
    bn_stats<<<3 * C, 256>>>(gq, betaq, gk, betak, gv, betav);
    gram_gemm<<<dim3(2, 2, SPLIT * B), 256>>>();
    m_fix<<<dim3(C, B), 256>>>();
    out_gemm<<<dim3(32, 2, B), 256>>>(out);
}

// round 5
// speedup vs baseline: 2.2303x; 1.1139x over previous
#include <cuda_runtime.h>
#include <cuda_bf16.h>
#include <cstdint>

#define B 8
#define C 256
#define HW 4096
#define BN_EPS 1e-5f
#define SPLIT 16
#define NT 32
#define PLANE 16384          // 128 rows x 128 bytes
#define SW128(o) ((o) ^ (((o) >> 3) & 0x70))

// ---- device scratch ----
__device__ uint32_t g_Yhi[3][(size_t)B * C * HW / 2];
__device__ uint32_t g_Ylo[3][(size_t)B * C * HW / 2];
__device__ float    g_a[3][C], g_d[3][C];
__device__ float    g_S[3][B * C];
__device__ float    g_Psum[3][(size_t)B * NT * C];
__device__ float    g_Psum2[3][(size_t)B * NT * C];
__device__ float    g_Gpart[SPLIT][(size_t)B * C * C];
__device__ uint32_t g_M2hi[(size_t)B * C * C / 2];
__device__ uint32_t g_M2lo[(size_t)B * C * C / 2];
__device__ float    g_r[B * C];

// ---- helpers ----
__device__ __forceinline__ uint32_t smaddr(const void* p) {
    return (uint32_t)__cvta_generic_to_shared(p);
}
__device__ __forceinline__ void split2(float e0, float e1, uint32_t& hi, uint32_t& lo) {
    __nv_bfloat16 h0 = __float2bfloat16(e0);
    __nv_bfloat16 h1 = __float2bfloat16(e1);
    __nv_bfloat162 hp = __halves2bfloat162(h0, h1);
    __nv_bfloat162 lp = __floats2bfloat162_rn(e0 - __bfloat162float(h0),
                                              e1 - __bfloat162float(h1));
    hi = *reinterpret_cast<uint32_t*>(&hp);
    lo = *reinterpret_cast<uint32_t*>(&lp);
}
__device__ __forceinline__ void mma16816(float* c, const uint32_t* a, const uint32_t* b) {
    asm volatile(
        "mma.sync.aligned.m16n8k16.row.col.f32.bf16.bf16.f32 "
        "{%0,%1,%2,%3}, {%4,%5,%6,%7}, {%8,%9}, {%0,%1,%2,%3};\n"
        : "+f"(c[0]), "+f"(c[1]), "+f"(c[2]), "+f"(c[3])
        : "r"(a[0]), "r"(a[1]), "r"(a[2]), "r"(a[3]), "r"(b[0]), "r"(b[1]));
}
// ldmatrix x4 from [row][64 bf16] SW128 tile; 16 rows starting row0, 32B of k at kb
__device__ __forceinline__ void ldfrag(uint32_t* r, uint32_t base, int row0, int kb, int lane) {
    int rl = row0 + (lane & 15);
    int cb = kb + ((lane >> 4) << 4);
    uint32_t a = base + (uint32_t)SW128(rl * 128 + cb);
    asm volatile("ldmatrix.sync.aligned.m8n8.x4.shared.b16 {%0,%1,%2,%3}, [%4];"
                 : "=r"(r[0]), "=r"(r[1]), "=r"(r[2]), "=r"(r[3]) : "r"(a));
}
// one K=64 chunk: 3-term hi/lo bf16 split, warp tile m32 x n64
__device__ __forceinline__ void mma_chunk(
    float (*acc)[8][4], uint32_t Ah, uint32_t Al, uint32_t Bh, uint32_t Bl,
    int lane, int wm, int wn)
{
#pragma unroll
    for (int ks = 0; ks < 4; ks++) {
        const int kb = ks * 32;
        uint32_t ah[2][4], al[2][4];
        ldfrag(ah[0], Ah, wm,      kb, lane);
        ldfrag(ah[1], Ah, wm + 16, kb, lane);
        ldfrag(al[0], Al, wm,      kb, lane);
        ldfrag(al[1], Al, wm + 16, kb, lane);
#pragma unroll
        for (int j = 0; j < 4; j++) {
            uint32_t bh[4], bl[4];
            ldfrag(bh, Bh, wn + j * 16, kb, lane);
            ldfrag(bl, Bl, wn + j * 16, kb, lane);
            uint32_t b0h[2] = {bh[0], bh[2]}, b1h[2] = {bh[1], bh[3]};
            uint32_t b0l[2] = {bl[0], bl[2]}, b1l[2] = {bl[1], bl[3]};
#pragma unroll
            for (int i = 0; i < 2; i++) {
                mma16816(acc[i][2 * j],     ah[i], b0h);
                mma16816(acc[i][2 * j],     ah[i], b0l);
                mma16816(acc[i][2 * j],     al[i], b0h);
                mma16816(acc[i][2 * j + 1], ah[i], b1h);
                mma16816(acc[i][2 * j + 1], ah[i], b1l);
                mma16816(acc[i][2 * j + 1], al[i], b1h);
            }
        }
    }
}
__device__ __forceinline__ void cp16(uint32_t dst, const void* src) {
    asm volatile("cp.async.cg.shared.global [%0], [%1], 16;"
                 :: "r"(dst), "l"((unsigned long long)__cvta_generic_to_global(src)) : "memory");
}
__device__ __forceinline__ void cp_commit() {
    asm volatile("cp.async.commit_group;" ::: "memory");
}
template <int N>
__device__ __forceinline__ void cp_wait() {
    asm volatile("cp.async.wait_group %0;" :: "n"(N) : "memory");
}

// ---------------------------------------------------------------------------
// K1: proj.  Y[p][b] = W_p * x[b] + bias.  grid (32, 2, 24), 256 thr, 64KB smem
// ---------------------------------------------------------------------------
__global__ __launch_bounds__(256, 1) void proj_gemm(
    const float* __restrict__ x,
    const float* __restrict__ Wq, const float* __restrict__ bq,
    const float* __restrict__ Wk, const float* __restrict__ bk,
    const float* __restrict__ Wv, const float* __restrict__ bv)
{
    extern __shared__ char smraw[];
    uint32_t sa0 = smaddr(smraw);
    char* sm = smraw + ((1024u - (sa0 & 1023u)) & 1023u);
    const uint32_t Ah = smaddr(sm), Al = Ah + PLANE, Bh = Ah + 2 * PLANE, Bl = Ah + 3 * PLANE;

    const int p = blockIdx.z >> 3, b = blockIdx.z & 7;
    const float* W    = (p == 0) ? Wq : (p == 1) ? Wk : Wv;
    const float* bias = (p == 0) ? bq : (p == 1) ? bk : bv;
    const float* xb = x + (size_t)b * C * HW;

    const int tid = threadIdx.x, lane = tid & 31, wid = tid >> 5;
    const int nt = blockIdx.x, n0 = nt * 128, m0 = blockIdx.y * 128;
    const int wm = (wid & 3) * 32, wn = (wid >> 2) * 64;

    float2 wpre[16];
    float xp0[16], xp1[16];
#pragma unroll
    for (int i = 0; i < 16; i++) {
        int idx = i * 256 + tid;
        int r = idx >> 5, k2 = idx & 31;
        wpre[i] = *(const float2*)&W[(size_t)(m0 + r) * C + 2 * k2];
        int xk2 = idx >> 7, n = idx & 127;
        xp0[i] = xb[(size_t)(2 * xk2) * HW + n0 + n];
        xp1[i] = xb[(size_t)(2 * xk2 + 1) * HW + n0 + n];
    }

    float acc[2][8][4] = {};
    for (int kt = 0; kt < 4; kt++) {
#pragma unroll
        for (int i = 0; i < 16; i++) {
            int idx = i * 256 + tid;
            int r = idx >> 5, k2 = idx & 31;
            uint32_t hi, lo; split2(wpre[i].x, wpre[i].y, hi, lo);
            int off = SW128(r * 128 + k2 * 4);
            *(uint32_t*)(sm + off) = hi;
            *(uint32_t*)(sm + PLANE + off) = lo;
            int xk2 = idx >> 7, n = idx & 127;
            split2(xp0[i], xp1[i], hi, lo);
            off = SW128(n * 128 + xk2 * 4);
            *(uint32_t*)(sm + 2 * PLANE + off) = hi;
            *(uint32_t*)(sm + 3 * PLANE + off) = lo;
        }
        __syncthreads();
        if (kt < 3) {
            const int k0 = (kt + 1) * 64;
#pragma unroll
            for (int i = 0; i < 16; i++) {
                int idx = i * 256 + tid;
                int r = idx >> 5, k2 = idx & 31;
                wpre[i] = *(const float2*)&W[(size_t)(m0 + r) * C + k0 + 2 * k2];
                int xk2 = idx >> 7, n = idx & 127;
                xp0[i] = xb[(size_t)(k0 + 2 * xk2) * HW + n0 + n];
                xp1[i] = xb[(size_t)(k0 + 2 * xk2 + 1) * HW + n0 + n];
            }
        }
        mma_chunk(acc, Ah, Al, Bh, Bl, lane, wm, wn);
        __syncthreads();
    }

    // epilogue: +bias, plane stores, per-row partial stats
    const int g = lane >> 2, tg = lane & 3;
    float rsum[4] = {}, rsum2[4] = {};
#pragma unroll
    for (int i = 0; i < 2; i++)
#pragma unroll
        for (int j = 0; j < 8; j++) {
            int r0 = m0 + wm + i * 16 + g;
            int cc = n0 + wn + j * 8 + tg * 2;
            uint32_t hi, lo;
            float bi = bias[r0];
            float y0 = acc[i][j][0] + bi, y1 = acc[i][j][1] + bi;
            rsum[i * 2]  += y0 + y1;
            rsum2[i * 2] += y0 * y0 + y1 * y1;
            split2(y0, y1, hi, lo);
            size_t off = ((size_t)(b * C + r0) * HW + cc) >> 1;
            g_Yhi[p][off] = hi; g_Ylo[p][off] = lo;
            int r1 = r0 + 8;
            bi = bias[r1];
            y0 = acc[i][j][2] + bi; y1 = acc[i][j][3] + bi;
            rsum[i * 2 + 1]  += y0 + y1;
            rsum2[i * 2 + 1] += y0 * y0 + y1 * y1;
            split2(y0, y1, hi, lo);
            off = ((size_t)(b * C + r1) * HW + cc) >> 1;
            g_Yhi[p][off] = hi; g_Ylo[p][off] = lo;
        }
#pragma unroll
    for (int q = 0; q < 4; q++) {
        rsum[q]  += __shfl_xor_sync(0xffffffffu, rsum[q], 1);
        rsum[q]  += __shfl_xor_sync(0xffffffffu, rsum[q], 2);
        rsum2[q] += __shfl_xor_sync(0xffffffffu, rsum2[q], 1);
        rsum2[q] += __shfl_xor_sync(0xffffffffu, rsum2[q], 2);
    }
    float* sb  = (float*)sm;
    float* sb2 = (float*)(sm + 2048);
    if (tg == 0) {
        const int half = wn >> 6;
#pragma unroll
        for (int q = 0; q < 4; q++) {
            int r = wm + (q >> 1) * 16 + (q & 1) * 8 + g;
            sb[r * 2 + half]  = rsum[q];
            sb2[r * 2 + half] = rsum2[q];
        }
    }
    __syncthreads();
    if (tid < 128) {
        size_t off = ((size_t)b * NT + nt) * C + m0 + tid;
        g_Psum[p][off]  = sb[tid * 2] + sb[tid * 2 + 1];
        g_Psum2[p][off] = sb2[tid * 2] + sb2[tid * 2 + 1];
    }
}

// ---------------------------------------------------------------------------
// K2: BN affine from partial stats. grid 3*C, 256.
// ---------------------------------------------------------------------------
__global__ __launch_bounds__(256) void bn_stats(
    const float* __restrict__ gq, const float* __restrict__ betaq,
    const float* __restrict__ gk, const float* __restrict__ betak,
    const float* __restrict__ gv, const float* __restrict__ betav)
{
    __shared__ float bs[8], bs2[8];
    const int p = blockIdx.x / C, c = blockIdx.x % C;
    const int lane = threadIdx.x & 31, b = threadIdx.x >> 5;

    size_t off = ((size_t)b * NT + lane) * C + c;
    float s  = g_Psum[p][off];
    float s2 = g_Psum2[p][off];
#pragma unroll
    for (int o = 16; o > 0; o >>= 1) {
        s  += __shfl_xor_sync(0xffffffffu, s, o);
        s2 += __shfl_xor_sync(0xffffffffu, s2, o);
    }
    if (lane == 0) {
        g_S[p][b * C + c] = s;
        bs[b] = s; bs2[b] = s2;
    }
    __syncthreads();
    if (threadIdx.x == 0) {
        float ts = 0.f, ts2 = 0.f;
#pragma unroll
        for (int i = 0; i < 8; i++) { ts += bs[i]; ts2 += bs2[i]; }
        const float inv_n = 1.f / (float)(B * HW);
        float mu  = ts * inv_n;
        float var = ts2 * inv_n - mu * mu;
        float inv = rsqrtf(var + BN_EPS);
        const float* gg = (p == 0) ? gq : (p == 1) ? gk : gv;
        const float* be = (p == 0) ? betaq : (p == 1) ? betak : betav;
        float a = gg[c] * inv;
        g_a[p][c] = a;
        g_d[p][c] = be[c] - mu * a;
    }
}

// ---------------------------------------------------------------------------
// K3: Gram = Vraw * Kraw^T, split-K=16. grid (2,2,128), 256 thr, 128KB smem.
// cp.async double-buffered.
// ---------------------------------------------------------------------------
__global__ __launch_bounds__(256, 1) void gram_gemm()
{
    extern __shared__ char smraw[];
    uint32_t sa0 = smaddr(smraw);
    char* sm = smraw + ((1024u - (sa0 & 1023u)) & 1023u);
    const uint32_t sb = smaddr(sm);   // [buf][4 planes][PLANE]

    const int tid = threadIdx.x, lane = tid & 31, wid = tid >> 5;
    const int s = blockIdx.z >> 3, b = blockIdx.z & 7;
    const int m0 = blockIdx.y * 128, n0 = blockIdx.x * 128;
    const int wm = (wid & 3) * 32, wn = (wid >> 2) * 64;

    const uint32_t* Vh = g_Yhi[2] + (size_t)b * C * (HW / 2);
    const uint32_t* Vl = g_Ylo[2] + (size_t)b * C * (HW / 2);
    const uint32_t* Kh = g_Yhi[1] + (size_t)b * C * (HW / 2);
    const uint32_t* Kl = g_Ylo[1] + (size_t)b * C * (HW / 2);

    auto stage = [&](int kt, int t) {
        const int kw = s * 128 + kt * 32;
        const uint32_t base = sb + t * 4 * PLANE;
#pragma unroll
        for (int i = 0; i < 4; i++) {
            int idx = i * 256 + tid;
            int r = idx >> 3, u = idx & 7;
            uint32_t doff = (uint32_t)SW128(r * 128 + u * 16);
            size_t sA = (size_t)(m0 + r) * (HW / 2) + kw + u * 4;
            size_t sB = (size_t)(n0 + r) * (HW / 2) + kw + u * 4;
            cp16(base + doff,             Vh + sA);
            cp16(base + PLANE + doff,     Vl + sA);
            cp16(base + 2 * PLANE + doff, Kh + sB);
            cp16(base + 3 * PLANE + doff, Kl + sB);
        }
        cp_commit();
    };

    stage(0, 0);
    float acc[2][8][4] = {};
    for (int kt = 0; kt < 4; kt++) {
        if (kt < 3) { stage(kt + 1, (kt + 1) & 1); cp_wait<1>(); }
        else        { cp_wait<0>(); }
        __syncthreads();
        const uint32_t base = sb + (kt & 1) * 4 * PLANE;
        mma_chunk(acc, base, base + PLANE, base + 2 * PLANE, base + 3 * PLANE,
                  lane, wm, wn);
        __syncthreads();
    }

    float* Gp = &g_Gpart[s][(size_t)b * C * C];
    const int g = lane >> 2, tg = lane & 3;
#pragma unroll
    for (int i = 0; i < 2; i++)
#pragma unroll
        for (int j = 0; j < 8; j++) {
            int r0 = m0 + wm + i * 16 + g;
            int cc = n0 + wn + j * 8 + tg * 2;
            *(float2*)&Gp[(size_t)r0 * C + cc] = make_float2(acc[i][j][0], acc[i][j][1]);
            *(float2*)&Gp[(size_t)(r0 + 8) * C + cc] = make_float2(acc[i][j][2], acc[i][j][3]);
        }
}

// ---------------------------------------------------------------------------
// K4: reduce Gram partials + BN fold.  grid (C, B), 256.
// ---------------------------------------------------------------------------
__global__ __launch_bounds__(256) void m_fix()
{
    __shared__ float red[256];
    const int m = blockIdx.x, b = blockIdx.y;
    const int c = threadIdx.x;
    __nv_bfloat16* M2h = reinterpret_cast<__nv_bfloat16*>(g_M2hi);
    __nv_bfloat16* M2l = reinterpret_cast<__nv_bfloat16*>(g_M2lo);

    const float av = g_a[2][m], dv = g_d[2][m];
    const float SV = g_S[2][b * C + m];

    const size_t rowoff = (size_t)b * C * C + (size_t)m * C + c;
    float e = 0.f;
#pragma unroll
    for (int s = 0; s < SPLIT; s++)
        e += g_Gpart[s][rowoff];

    float ak = g_a[1][c], dk = g_d[1][c];
    float SK = g_S[1][b * C + c];
    float M = av * ak * e + av * dk * SV + dv * ak * SK + 4096.f * dv * dk;
    float M2 = 0.125f * M * g_a[0][c];
    __nv_bfloat16 hi = __float2bfloat16(M2);
    __nv_bfloat16 lo = __float2bfloat16(M2 - __bfloat162float(hi));
    size_t off = (size_t)(b * C + m) * C + c;
    M2h[off] = hi; M2l[off] = lo;

    red[c] = M * g_d[0][c];
    __syncthreads();
    for (int o = 128; o > 0; o >>= 1) {
        if (c < o) red[c] += red[c + o];
        __syncthreads();
    }
    if (c == 0) g_r[b * C + m] = 0.125f * red[0];
}

// ---------------------------------------------------------------------------
// K5: out = M2 * Qraw + r.  grid (32, 2, 8), 256 thr, 128KB smem.
// A via cp.async; B via LDG+byte_perm transpose STS; double-buffered.
// ---------------------------------------------------------------------------
__global__ __launch_bounds__(256, 1) void out_gemm(float* __restrict__ out)
{
    extern __shared__ char smraw[];
    uint32_t sa0 = smaddr(smraw);
    char* sm = smraw + ((1024u - (sa0 & 1023u)) & 1023u);
    const uint32_t sbA = smaddr(sm);                  // [buf][hi,lo][PLANE]
    const uint32_t sbB = sbA + 4 * PLANE;             // [buf][hi,lo][PLANE]
    char* smB = sm + 4 * PLANE;

    const int tid = threadIdx.x, lane = tid & 31, wid = tid >> 5;
    const int b = blockIdx.z;
    const int n0 = blockIdx.x * 128, m0 = blockIdx.y * 128;
    const int wm = (wid & 3) * 32, wn = (wid >> 2) * 64;

    const uint32_t* Qh = g_Yhi[0] + (size_t)b * C * (HW / 2);
    const uint32_t* Ql = g_Ylo[0] + (size_t)b * C * (HW / 2);

    auto stageA = [&](int kt, int t) {
        const uint32_t base = sbA + t * 2 * PLANE;
#pragma unroll
        for (int i = 0; i < 4; i++) {
            int idx = i * 256 + tid;
            int r = idx >> 3, u = idx & 7;
            uint32_t doff = (uint32_t)SW128(r * 128 + u * 16);
            size_t srco = (size_t)(b * C + m0 + r) * (C / 2) + kt * 32 + u * 4;
            cp16(base + doff,         g_M2hi + srco);
            cp16(base + PLANE + doff, g_M2lo + srco);
        }
        cp_commit();
    };
    auto stageB = [&](int kt, int t) {
        char* base = smB + t * 2 * PLANE;
        const int k0 = kt * 64;
#pragma unroll
        for (int i = 0; i < 8; i++) {
            int idx = i * 256 + tid;
            int k2 = idx >> 6, np = idx & 63;
            size_t srco = (size_t)(k0 + 2 * k2) * (HW / 2) + (n0 >> 1) + np;
            uint32_t u0 = Qh[srco], u1 = Qh[srco + HW / 2];
            int offE = SW128((2 * np) * 128 + k2 * 4);
            int offO = SW128((2 * np + 1) * 128 + k2 * 4);
            *(uint32_t*)(base + offE) = __byte_perm(u0, u1, 0x5410);
            *(uint32_t*)(base + offO) = __byte_perm(u0, u1, 0x7632);
            uint32_t l0 = Ql[srco], l1 = Ql[srco + HW / 2];
            *(uint32_t*)(base + PLANE + offE) = __byte_perm(l0, l1, 0x5410);
            *(uint32_t*)(base + PLANE + offO) = __byte_perm(l0, l1, 0x7632);
        }
    };

    stageA(0, 0);
    stageB(0, 0);
    float acc[2][8][4] = {};
    for (int kt = 0; kt < 4; kt++) {
        if (kt < 3) {
            stageA(kt + 1, (kt + 1) & 1);
            stageB(kt + 1, (kt + 1) & 1);
            cp_wait<1>();
        } else {
            cp_wait<0>();
        }
        __syncthreads();
        const uint32_t bA = sbA + (kt & 1) * 2 * PLANE;
        const uint32_t bB = sbB + (kt & 1) * 2 * PLANE;
        mma_chunk(acc, bA, bA + PLANE, bB, bB + PLANE, lane, wm, wn);
        __syncthreads();
    }

    const int g = lane >> 2, tg = lane & 3;
#pragma unroll
    for (int i = 0; i < 2; i++)
#pragma unroll
        for (int j = 0; j < 8; j++) {
            int r0 = m0 + wm + i * 16 + g;
            int cc = n0 + wn + j * 8 + tg * 2;
            float rr = g_r[b * C + r0];
            *(float2*)&out[(size_t)(b * C + r0) * HW + cc] =
                make_float2(acc[i][j][0] + rr, acc[i][j][1] + rr);
            rr = g_r[b * C + r0 + 8];
            *(float2*)&out[(size_t)(b * C + r0 + 8) * HW + cc] =
                make_float2(acc[i][j][2] + rr, acc[i][j][3] + rr);
        }
}

// ---------------------------------------------------------------------------
extern "C" void kernel_launch(void* const* d_in, const int* in_sizes, int n_in,
                              void* d_out, int out_size)
{
    const float* x     = (const float*)d_in[0];
    const float* Wq    = (const float*)d_in[1];
    const float* bq    = (const float*)d_in[2];
    const float* gq    = (const float*)d_in[3];
    const float* betaq = (const float*)d_in[4];
    const float* Wk    = (const float*)d_in[5];
    const float* bk    = (const float*)d_in[6];
    const float* gk    = (const float*)d_in[7];
    const float* betak = (const float*)d_in[8];
    const float* Wv    = (const float*)d_in[9];
    const float* bv    = (const float*)d_in[10];
    const float* gv    = (const float*)d_in[11];
    const float* betav = (const float*)d_in[12];
    float* out = (float*)d_out;

    const int smProj = 4 * PLANE + 1024;
    const int smGO   = 8 * PLANE + 1024;
    static int attr_done = 0;
    if (!attr_done) {
        cudaFuncSetAttribute(proj_gemm, cudaFuncAttributeMaxDynamicSharedMemorySize, smProj);
        cudaFuncSetAttribute(gram_gemm, cudaFuncAttributeMaxDynamicSharedMemorySize, smGO);
        cudaFuncSetAttribute(out_gemm,  cudaFuncAttributeMaxDynamicSharedMemorySize, smGO);
        attr_done = 1;
    }

    proj_gemm<<<dim3(32, 2, 3 * B), 256, smProj>>>(x, Wq, bq, Wk, bk, Wv, bv);
    bn_stats<<<3 * C, 256>>>(gq, betaq, gk, betak, gv, betav);
    gram_gemm<<<dim3(2, 2, SPLIT * B), 256, smGO>>>();
    m_fix<<<dim3(C, B), 256>>>();
    out_gemm<<<dim3(32, 2, B), 256, smGO>>>(out);
}

// round 6
// speedup vs baseline: 2.5108x; 1.1258x over previous
#include <cuda_runtime.h>
#include <cuda_bf16.h>
#include <cstdint>

#define B 8
#define C 256
#define HW 4096
#define BN_EPS 1e-5f
#define SPLIT 16
#define NT 32
#define PLANE 16384          // 128 rows x 128 bytes
#define SW128(o) ((o) ^ (((o) >> 3) & 0x70))

// ---- device scratch ----
__device__ uint32_t g_Yhi[3][(size_t)B * C * HW / 2];
__device__ uint32_t g_Ylo[3][(size_t)B * C * HW / 2];
__device__ uint32_t g_Xsp[B][NT][4][2][4096];   // x planes, swizzled smem image
__device__ uint32_t g_Wsp[3][2][4][2][4096];    // W planes, swizzled smem image
__device__ float    g_a[3][C], g_d[3][C];
__device__ float    g_S[3][B * C];
__device__ float    g_Psum[3][(size_t)B * NT * C];
__device__ float    g_Psum2[3][(size_t)B * NT * C];
__device__ float    g_Gpart[SPLIT][(size_t)B * C * C];
__device__ uint32_t g_M2hi[(size_t)B * C * C / 2];
__device__ uint32_t g_M2lo[(size_t)B * C * C / 2];
__device__ float    g_r[B * C];

// ---- helpers ----
__device__ __forceinline__ uint32_t smaddr(const void* p) {
    return (uint32_t)__cvta_generic_to_shared(p);
}
__device__ __forceinline__ void split2(float e0, float e1, uint32_t& hi, uint32_t& lo) {
    __nv_bfloat16 h0 = __float2bfloat16(e0);
    __nv_bfloat16 h1 = __float2bfloat16(e1);
    __nv_bfloat162 hp = __halves2bfloat162(h0, h1);
    __nv_bfloat162 lp = __floats2bfloat162_rn(e0 - __bfloat162float(h0),
                                              e1 - __bfloat162float(h1));
    hi = *reinterpret_cast<uint32_t*>(&hp);
    lo = *reinterpret_cast<uint32_t*>(&lp);
}
__device__ __forceinline__ void mma16816(float* c, const uint32_t* a, const uint32_t* b) {
    asm volatile(
        "mma.sync.aligned.m16n8k16.row.col.f32.bf16.bf16.f32 "
        "{%0,%1,%2,%3}, {%4,%5,%6,%7}, {%8,%9}, {%0,%1,%2,%3};\n"
        : "+f"(c[0]), "+f"(c[1]), "+f"(c[2]), "+f"(c[3])
        : "r"(a[0]), "r"(a[1]), "r"(a[2]), "r"(a[3]), "r"(b[0]), "r"(b[1]));
}
__device__ __forceinline__ void ldfrag(uint32_t* r, uint32_t base, int row0, int kb, int lane) {
    int rl = row0 + (lane & 15);
    int cb = kb + ((lane >> 4) << 4);
    uint32_t a = base + (uint32_t)SW128(rl * 128 + cb);
    asm volatile("ldmatrix.sync.aligned.m8n8.x4.shared.b16 {%0,%1,%2,%3}, [%4];"
                 : "=r"(r[0]), "=r"(r[1]), "=r"(r[2]), "=r"(r[3]) : "r"(a));
}
__device__ __forceinline__ void mma_chunk(
    float (*acc)[8][4], uint32_t Ah, uint32_t Al, uint32_t Bh, uint32_t Bl,
    int lane, int wm, int wn)
{
#pragma unroll
    for (int ks = 0; ks < 4; ks++) {
        const int kb = ks * 32;
        uint32_t ah[2][4], al[2][4];
        ldfrag(ah[0], Ah, wm,      kb, lane);
        ldfrag(ah[1], Ah, wm + 16, kb, lane);
        ldfrag(al[0], Al, wm,      kb, lane);
        ldfrag(al[1], Al, wm + 16, kb, lane);
#pragma unroll
        for (int j = 0; j < 4; j++) {
            uint32_t bh[4], bl[4];
            ldfrag(bh, Bh, wn + j * 16, kb, lane);
            ldfrag(bl, Bl, wn + j * 16, kb, lane);
            uint32_t b0h[2] = {bh[0], bh[2]}, b1h[2] = {bh[1], bh[3]};
            uint32_t b0l[2] = {bl[0], bl[2]}, b1l[2] = {bl[1], bl[3]};
#pragma unroll
            for (int i = 0; i < 2; i++) {
                mma16816(acc[i][2 * j],     ah[i], b0h);
                mma16816(acc[i][2 * j],     ah[i], b0l);
                mma16816(acc[i][2 * j],     al[i], b0h);
                mma16816(acc[i][2 * j + 1], ah[i], b1h);
                mma16816(acc[i][2 * j + 1], ah[i], b1l);
                mma16816(acc[i][2 * j + 1], al[i], b1h);
            }
        }
    }
}
__device__ __forceinline__ void cp16(uint32_t dst, const void* src) {
    asm volatile("cp.async.cg.shared.global [%0], [%1], 16;"
                 :: "r"(dst), "l"((unsigned long long)__cvta_generic_to_global(src)) : "memory");
}
__device__ __forceinline__ void cp_commit() {
    asm volatile("cp.async.commit_group;" ::: "memory");
}
template <int N>
__device__ __forceinline__ void cp_wait() {
    asm volatile("cp.async.wait_group %0;" :: "n"(N) : "memory");
}

// ---------------------------------------------------------------------------
// K0a: W split -> swizzled smem-image planes. grid 24 (p, mh, kt), 256 thr.
// ---------------------------------------------------------------------------
__global__ __launch_bounds__(256) void wsplit(
    const float* __restrict__ Wq, const float* __restrict__ Wk,
    const float* __restrict__ Wv)
{
    const int p = blockIdx.x >> 3, rem = blockIdx.x & 7;
    const int mh = rem >> 2, kt = rem & 3;
    const float* W = (p == 0) ? Wq : (p == 1) ? Wk : Wv;
    const int m0 = mh * 128, k0 = kt * 64;
    char* dh = (char*)g_Wsp[p][mh][kt][0];
    char* dl = (char*)g_Wsp[p][mh][kt][1];
    const int tid = threadIdx.x;
#pragma unroll
    for (int i = 0; i < 16; i++) {
        int idx = i * 256 + tid;
        int r = idx >> 5, k2 = idx & 31;
        float2 w2 = *(const float2*)&W[(size_t)(m0 + r) * C + k0 + 2 * k2];
        uint32_t hi, lo; split2(w2.x, w2.y, hi, lo);
        int off = SW128(r * 128 + k2 * 4);
        *(uint32_t*)(dh + off) = hi;
        *(uint32_t*)(dl + off) = lo;
    }
}

// ---------------------------------------------------------------------------
// K0b: x split + transpose -> swizzled smem-image planes [b][nt][kt].
// grid (32 nt, 4 kt, 8 b), 256 thr.  smem transpose tile 64c x 128n.
// ---------------------------------------------------------------------------
__global__ __launch_bounds__(256) void xsplit(const float* __restrict__ x)
{
    __shared__ float xs[64][129];
    const int nt = blockIdx.x, kt = blockIdx.y, b = blockIdx.z;
    const int n0 = nt * 128, c0 = kt * 64;
    const int tid = threadIdx.x;
    const float* xb = x + (size_t)b * C * HW;

    // coalesced load: 64 rows x 128 floats
#pragma unroll
    for (int i = 0; i < 8; i++) {
        int idx = i * 256 + tid;          // float4 index
        int c = idx >> 5, f4 = idx & 31;
        float4 v = *(const float4*)&xb[(size_t)(c0 + c) * HW + n0 + f4 * 4];
        xs[c][f4 * 4 + 0] = v.x; xs[c][f4 * 4 + 1] = v.y;
        xs[c][f4 * 4 + 2] = v.z; xs[c][f4 * 4 + 3] = v.w;
    }
    __syncthreads();

    char* dh = (char*)g_Xsp[b][nt][kt][0];
    char* dl = (char*)g_Xsp[b][nt][kt][1];
#pragma unroll
    for (int i = 0; i < 16; i++) {
        int idx = i * 256 + tid;
        int n = idx >> 5, k2 = idx & 31;
        uint32_t hi, lo; split2(xs[2 * k2][n], xs[2 * k2 + 1][n], hi, lo);
        int off = SW128(n * 128 + k2 * 4);
        *(uint32_t*)(dh + off) = hi;
        *(uint32_t*)(dl + off) = lo;
    }
}

// ---------------------------------------------------------------------------
// K1: proj.  Y[p][b] = W_p * x[b] + bias.  Pure cp.async from pre-swizzled
// planes, double-buffered.  grid (32, 2, 24), 256 thr, 128KB smem.
// ---------------------------------------------------------------------------
__global__ __launch_bounds__(256, 1) void proj_gemm(
    const float* __restrict__ bq, const float* __restrict__ bk,
    const float* __restrict__ bv)
{
    extern __shared__ char smraw[];
    uint32_t sa0 = smaddr(smraw);
    char* sm = smraw + ((1024u - (sa0 & 1023u)) & 1023u);
    const uint32_t sb = smaddr(sm);   // [buf][Ah,Al,Bh,Bl][PLANE]

    const int p = blockIdx.z >> 3, b = blockIdx.z & 7;
    const float* bias = (p == 0) ? bq : (p == 1) ? bk : bv;
    const int tid = threadIdx.x, lane = tid & 31, wid = tid >> 5;
    const int nt = blockIdx.x, mh = blockIdx.y;
    const int n0 = nt * 128, m0 = mh * 128;
    const int wm = (wid & 3) * 32, wn = (wid >> 2) * 64;

    auto stage = [&](int kt, int t) {
        const uint32_t base = sb + t * 4 * PLANE;
        const uint32_t* Ah = g_Wsp[p][mh][kt][0];
        const uint32_t* Al = g_Wsp[p][mh][kt][1];
        const uint32_t* Bh = g_Xsp[b][nt][kt][0];
        const uint32_t* Bl = g_Xsp[b][nt][kt][1];
#pragma unroll
        for (int i = 0; i < 4; i++) {
            int idx = i * 256 + tid;
            uint32_t doff = idx * 16;
            cp16(base + doff,             Ah + idx * 4);
            cp16(base + PLANE + doff,     Al + idx * 4);
            cp16(base + 2 * PLANE + doff, Bh + idx * 4);
            cp16(base + 3 * PLANE + doff, Bl + idx * 4);
        }
        cp_commit();
    };

    stage(0, 0);
    float acc[2][8][4] = {};
#pragma unroll
    for (int kt = 0; kt < 4; kt++) {
        if (kt < 3) { stage(kt + 1, (kt + 1) & 1); cp_wait<1>(); }
        else        { cp_wait<0>(); }
        __syncthreads();
        const uint32_t base = sb + (kt & 1) * 4 * PLANE;
        mma_chunk(acc, base, base + PLANE, base + 2 * PLANE, base + 3 * PLANE,
                  lane, wm, wn);
        __syncthreads();
    }

    // epilogue: +bias, plane stores, per-row partial stats
    const int g = lane >> 2, tg = lane & 3;
    float rsum[4] = {}, rsum2[4] = {};
#pragma unroll
    for (int i = 0; i < 2; i++)
#pragma unroll
        for (int j = 0; j < 8; j++) {
            int r0 = m0 + wm + i * 16 + g;
            int cc = n0 + wn + j * 8 + tg * 2;
            uint32_t hi, lo;
            float bi = bias[r0];
            float y0 = acc[i][j][0] + bi, y1 = acc[i][j][1] + bi;
            rsum[i * 2]  += y0 + y1;
            rsum2[i * 2] += y0 * y0 + y1 * y1;
            split2(y0, y1, hi, lo);
            size_t off = ((size_t)(b * C + r0) * HW + cc) >> 1;
            g_Yhi[p][off] = hi; g_Ylo[p][off] = lo;
            int r1 = r0 + 8;
            bi = bias[r1];
            y0 = acc[i][j][2] + bi; y1 = acc[i][j][3] + bi;
            rsum[i * 2 + 1]  += y0 + y1;
            rsum2[i * 2 + 1] += y0 * y0 + y1 * y1;
            split2(y0, y1, hi, lo);
            off = ((size_t)(b * C + r1) * HW + cc) >> 1;
            g_Yhi[p][off] = hi; g_Ylo[p][off] = lo;
        }
#pragma unroll
    for (int q = 0; q < 4; q++) {
        rsum[q]  += __shfl_xor_sync(0xffffffffu, rsum[q], 1);
        rsum[q]  += __shfl_xor_sync(0xffffffffu, rsum[q], 2);
        rsum2[q] += __shfl_xor_sync(0xffffffffu, rsum2[q], 1);
        rsum2[q] += __shfl_xor_sync(0xffffffffu, rsum2[q], 2);
    }
    float* sbf  = (float*)sm;
    float* sbf2 = (float*)(sm + 2048);
    if (tg == 0) {
        const int half = wn >> 6;
#pragma unroll
        for (int q = 0; q < 4; q++) {
            int r = wm + (q >> 1) * 16 + (q & 1) * 8 + g;
            sbf[r * 2 + half]  = rsum[q];
            sbf2[r * 2 + half] = rsum2[q];
        }
    }
    __syncthreads();
    if (tid < 128) {
        size_t off = ((size_t)b * NT + nt) * C + m0 + tid;
        g_Psum[p][off]  = sbf[tid * 2] + sbf[tid * 2 + 1];
        g_Psum2[p][off] = sbf2[tid * 2] + sbf2[tid * 2 + 1];
    }
}

// ---------------------------------------------------------------------------
// K2: BN affine from partial stats. grid 3*C, 256.
// ---------------------------------------------------------------------------
__global__ __launch_bounds__(256) void bn_stats(
    const float* __restrict__ gq, const float* __restrict__ betaq,
    const float* __restrict__ gk, const float* __restrict__ betak,
    const float* __restrict__ gv, const float* __restrict__ betav)
{
    __shared__ float bs[8], bs2[8];
    const int p = blockIdx.x / C, c = blockIdx.x % C;
    const int lane = threadIdx.x & 31, b = threadIdx.x >> 5;

    size_t off = ((size_t)b * NT + lane) * C + c;
    float s  = g_Psum[p][off];
    float s2 = g_Psum2[p][off];
#pragma unroll
    for (int o = 16; o > 0; o >>= 1) {
        s  += __shfl_xor_sync(0xffffffffu, s, o);
        s2 += __shfl_xor_sync(0xffffffffu, s2, o);
    }
    if (lane == 0) {
        g_S[p][b * C + c] = s;
        bs[b] = s; bs2[b] = s2;
    }
    __syncthreads();
    if (threadIdx.x == 0) {
        float ts = 0.f, ts2 = 0.f;
#pragma unroll
        for (int i = 0; i < 8; i++) { ts += bs[i]; ts2 += bs2[i]; }
        const float inv_n = 1.f / (float)(B * HW);
        float mu  = ts * inv_n;
        float var = ts2 * inv_n - mu * mu;
        float inv = rsqrtf(var + BN_EPS);
        const float* gg = (p == 0) ? gq : (p == 1) ? gk : gv;
        const float* be = (p == 0) ? betaq : (p == 1) ? betak : betav;
        float a = gg[c] * inv;
        g_a[p][c] = a;
        g_d[p][c] = be[c] - mu * a;
    }
}

// ---------------------------------------------------------------------------
// K3: Gram = Vraw * Kraw^T, split-K=16. grid (2,2,128), 256 thr, 128KB smem.
// ---------------------------------------------------------------------------
__global__ __launch_bounds__(256, 1) void gram_gemm()
{
    extern __shared__ char smraw[];
    uint32_t sa0 = smaddr(smraw);
    char* sm = smraw + ((1024u - (sa0 & 1023u)) & 1023u);
    const uint32_t sb = smaddr(sm);

    const int tid = threadIdx.x, lane = tid & 31, wid = tid >> 5;
    const int s = blockIdx.z >> 3, b = blockIdx.z & 7;
    const int m0 = blockIdx.y * 128, n0 = blockIdx.x * 128;
    const int wm = (wid & 3) * 32, wn = (wid >> 2) * 64;

    const uint32_t* Vh = g_Yhi[2] + (size_t)b * C * (HW / 2);
    const uint32_t* Vl = g_Ylo[2] + (size_t)b * C * (HW / 2);
    const uint32_t* Kh = g_Yhi[1] + (size_t)b * C * (HW / 2);
    const uint32_t* Kl = g_Ylo[1] + (size_t)b * C * (HW / 2);

    auto stage = [&](int kt, int t) {
        const int kw = s * 128 + kt * 32;
        const uint32_t base = sb + t * 4 * PLANE;
#pragma unroll
        for (int i = 0; i < 4; i++) {
            int idx = i * 256 + tid;
            int r = idx >> 3, u = idx & 7;
            uint32_t doff = (uint32_t)SW128(r * 128 + u * 16);
            size_t sA = (size_t)(m0 + r) * (HW / 2) + kw + u * 4;
            size_t sB = (size_t)(n0 + r) * (HW / 2) + kw + u * 4;
            cp16(base + doff,             Vh + sA);
            cp16(base + PLANE + doff,     Vl + sA);
            cp16(base + 2 * PLANE + doff, Kh + sB);
            cp16(base + 3 * PLANE + doff, Kl + sB);
        }
        cp_commit();
    };

    stage(0, 0);
    float acc[2][8][4] = {};
#pragma unroll
    for (int kt = 0; kt < 4; kt++) {
        if (kt < 3) { stage(kt + 1, (kt + 1) & 1); cp_wait<1>(); }
        else        { cp_wait<0>(); }
        __syncthreads();
        const uint32_t base = sb + (kt & 1) * 4 * PLANE;
        mma_chunk(acc, base, base + PLANE, base + 2 * PLANE, base + 3 * PLANE,
                  lane, wm, wn);
        __syncthreads();
    }

    float* Gp = &g_Gpart[s][(size_t)b * C * C];
    const int g = lane >> 2, tg = lane & 3;
#pragma unroll
    for (int i = 0; i < 2; i++)
#pragma unroll
        for (int j = 0; j < 8; j++) {
            int r0 = m0 + wm + i * 16 + g;
            int cc = n0 + wn + j * 8 + tg * 2;
            *(float2*)&Gp[(size_t)r0 * C + cc] = make_float2(acc[i][j][0], acc[i][j][1]);
            *(float2*)&Gp[(size_t)(r0 + 8) * C + cc] = make_float2(acc[i][j][2], acc[i][j][3]);
        }
}

// ---------------------------------------------------------------------------
// K4: reduce Gram partials + BN fold.  grid (C, B), 256.
// ---------------------------------------------------------------------------
__global__ __launch_bounds__(256) void m_fix()
{
    __shared__ float red[256];
    const int m = blockIdx.x, b = blockIdx.y;
    const int c = threadIdx.x;
    __nv_bfloat16* M2h = reinterpret_cast<__nv_bfloat16*>(g_M2hi);
    __nv_bfloat16* M2l = reinterpret_cast<__nv_bfloat16*>(g_M2lo);

    const float av = g_a[2][m], dv = g_d[2][m];
    const float SV = g_S[2][b * C + m];

    const size_t rowoff = (size_t)b * C * C + (size_t)m * C + c;
    float e = 0.f;
#pragma unroll
    for (int s = 0; s < SPLIT; s++)
        e += g_Gpart[s][rowoff];

    float ak = g_a[1][c], dk = g_d[1][c];
    float SK = g_S[1][b * C + c];
    float M = av * ak * e + av * dk * SV + dv * ak * SK + 4096.f * dv * dk;
    float M2 = 0.125f * M * g_a[0][c];
    __nv_bfloat16 hi = __float2bfloat16(M2);
    __nv_bfloat16 lo = __float2bfloat16(M2 - __bfloat162float(hi));
    size_t off = (size_t)(b * C + m) * C + c;
    M2h[off] = hi; M2l[off] = lo;

    red[c] = M * g_d[0][c];
    __syncthreads();
    for (int o = 128; o > 0; o >>= 1) {
        if (c < o) red[c] += red[c + o];
        __syncthreads();
    }
    if (c == 0) g_r[b * C + m] = 0.125f * red[0];
}

// ---------------------------------------------------------------------------
// K5: out = M2 * Qraw + r.  grid (32, 2, 8), 256 thr, 128KB smem.
// A cp.async double-buffered; B via register-prefetched LDG + PRMT STS.
// ---------------------------------------------------------------------------
__global__ __launch_bounds__(256, 1) void out_gemm(float* __restrict__ out)
{
    extern __shared__ char smraw[];
    uint32_t sa0 = smaddr(smraw);
    char* sm = smraw + ((1024u - (sa0 & 1023u)) & 1023u);
    const uint32_t sbA = smaddr(sm);                  // [buf][hi,lo][PLANE]
    const uint32_t sbB = sbA + 4 * PLANE;
    char* smB = sm + 4 * PLANE;

    const int tid = threadIdx.x, lane = tid & 31, wid = tid >> 5;
    const int b = blockIdx.z;
    const int n0 = blockIdx.x * 128, m0 = blockIdx.y * 128;
    const int wm = (wid & 3) * 32, wn = (wid >> 2) * 64;

    const uint32_t* Qh = g_Yhi[0] + (size_t)b * C * (HW / 2);
    const uint32_t* Ql = g_Ylo[0] + (size_t)b * C * (HW / 2);

    auto stageA = [&](int kt, int t) {
        const uint32_t base = sbA + t * 2 * PLANE;
#pragma unroll
        for (int i = 0; i < 4; i++) {
            int idx = i * 256 + tid;
            int r = idx >> 3, u = idx & 7;
            uint32_t doff = (uint32_t)SW128(r * 128 + u * 16);
            size_t srco = (size_t)(b * C + m0 + r) * (C / 2) + kt * 32 + u * 4;
            cp16(base + doff,         g_M2hi + srco);
            cp16(base + PLANE + doff, g_M2lo + srco);
        }
        cp_commit();
    };

    uint32_t bu0[2][8], bu1[2][8], bl0[2][8], bl1[2][8];
    auto ldgB = [&](int kt, int t) {
        const int k0 = kt * 64;
#pragma unroll
        for (int i = 0; i < 8; i++) {
            int idx = i * 256 + tid;
            int k2 = idx >> 6, np = idx & 63;
            size_t srco = (size_t)(k0 + 2 * k2) * (HW / 2) + (n0 >> 1) + np;
            bu0[t][i] = Qh[srco]; bu1[t][i] = Qh[srco + HW / 2];
            bl0[t][i] = Ql[srco]; bl1[t][i] = Ql[srco + HW / 2];
        }
    };
    auto stsB = [&](int t) {
        char* base = smB + t * 2 * PLANE;
#pragma unroll
        for (int i = 0; i < 8; i++) {
            int idx = i * 256 + tid;
            int k2 = idx >> 6, np = idx & 63;
            int offE = SW128((2 * np) * 128 + k2 * 4);
            int offO = SW128((2 * np + 1) * 128 + k2 * 4);
            *(uint32_t*)(base + offE) = __byte_perm(bu0[t][i], bu1[t][i], 0x5410);
            *(uint32_t*)(base + offO) = __byte_perm(bu0[t][i], bu1[t][i], 0x7632);
            *(uint32_t*)(base + PLANE + offE) = __byte_perm(bl0[t][i], bl1[t][i], 0x5410);
            *(uint32_t*)(base + PLANE + offO) = __byte_perm(bl0[t][i], bl1[t][i], 0x7632);
        }
    };

    ldgB(0, 0);
    stageA(0, 0);
    float acc[2][8][4] = {};
#pragma unroll
    for (int kt = 0; kt < 4; kt++) {
        stsB(kt & 1);
        if (kt < 3) {
            ldgB(kt + 1, (kt + 1) & 1);
            stageA(kt + 1, (kt + 1) & 1);
            cp_wait<1>();
        } else {
            cp_wait<0>();
        }
        __syncthreads();
        const uint32_t bA = sbA + (kt & 1) * 2 * PLANE;
        const uint32_t bB = sbB + (kt & 1) * 2 * PLANE;
        mma_chunk(acc, bA, bA + PLANE, bB, bB + PLANE, lane, wm, wn);
        __syncthreads();
    }

    const int g = lane >> 2, tg = lane & 3;
#pragma unroll
    for (int i = 0; i < 2; i++)
#pragma unroll
        for (int j = 0; j < 8; j++) {
            int r0 = m0 + wm + i * 16 + g;
            int cc = n0 + wn + j * 8 + tg * 2;
            float rr = g_r[b * C + r0];
            *(float2*)&out[(size_t)(b * C + r0) * HW + cc] =
                make_float2(acc[i][j][0] + rr, acc[i][j][1] + rr);
            rr = g_r[b * C + r0 + 8];
            *(float2*)&out[(size_t)(b * C + r0 + 8) * HW + cc] =
                make_float2(acc[i][j][2] + rr, acc[i][j][3] + rr);
        }
}

// ---------------------------------------------------------------------------
extern "C" void kernel_launch(void* const* d_in, const int* in_sizes, int n_in,
                              void* d_out, int out_size)
{
    const float* x     = (const float*)d_in[0];
    const float* Wq    = (const float*)d_in[1];
    const float* bq    = (const float*)d_in[2];
    const float* gq    = (const float*)d_in[3];
    const float* betaq = (const float*)d_in[4];
    const float* Wk    = (const float*)d_in[5];
    const float* bk    = (const float*)d_in[6];
    const float* gk    = (const float*)d_in[7];
    const float* betak = (const float*)d_in[8];
    const float* Wv    = (const float*)d_in[9];
    const float* bv    = (const float*)d_in[10];
    const float* gv    = (const float*)d_in[11];
    const float* betav = (const float*)d_in[12];
    float* out = (float*)d_out;

    const int smBig = 8 * PLANE + 1024;
    cudaFuncSetAttribute(proj_gemm, cudaFuncAttributeMaxDynamicSharedMemorySize, smBig);
    cudaFuncSetAttribute(gram_gemm, cudaFuncAttributeMaxDynamicSharedMemorySize, smBig);
    cudaFuncSetAttribute(out_gemm,  cudaFuncAttributeMaxDynamicSharedMemorySize, smBig);

    wsplit<<<24, 256>>>(Wq, Wk, Wv);
    xsplit<<<dim3(NT, 4, B), 256>>>(x);
    proj_gemm<<<dim3(32, 2, 3 * B), 256, smBig>>>(bq, bk, bv);
    bn_stats<<<3 * C, 256>>>(gq, betaq, gk, betak, gv, betav);
    gram_gemm<<<dim3(2, 2, SPLIT * B), 256, smBig>>>();
    m_fix<<<dim3(C, B), 256>>>();
    out_gemm<<<dim3(32, 2, B), 256, smBig>>>(out);
}

// round 7
// speedup vs baseline: 3.3456x; 1.3325x over previous
#include <cuda_runtime.h>
#include <cuda_fp16.h>
#include <cstdint>

#define B 8
#define C 256
#define HW 4096
#define BN_EPS 1e-5f
#define SPLIT 16
#define NT 32
#define PLANE 16384          // 128 rows x 128 bytes
#define SW128(o) ((o) ^ (((o) >> 3) & 0x70))

// ---- device scratch ----
__device__ uint32_t g_Yhi[3][(size_t)B * C * HW / 2];   // fp16 hi plane
__device__ uint32_t g_Ylo[3][(size_t)B * C * HW / 2];   // fp16 lo plane (p=1,2 only)
__device__ uint32_t g_Xsp[B][NT][4][4096];              // x hi plane, swizzled image
__device__ uint32_t g_Wsp[3][2][4][2][4096];            // W hi/lo planes, swizzled image
__device__ float    g_a[3][C], g_d[3][C];
__device__ float    g_S[3][B * C];
__device__ float    g_Psum[3][(size_t)B * NT * C];
__device__ float    g_Psum2[3][(size_t)B * NT * C];
__device__ float    g_Gpart[SPLIT][(size_t)B * C * C];
__device__ uint32_t g_M2hi[(size_t)B * C * C / 2];
__device__ uint32_t g_M2lo[(size_t)B * C * C / 2];
__device__ float    g_r[B * C];

// ---- helpers ----
__device__ __forceinline__ uint32_t smaddr(const void* p) {
    return (uint32_t)__cvta_generic_to_shared(p);
}
// fp16 hi/lo split of a float pair
__device__ __forceinline__ void split2h(float e0, float e1, uint32_t& hi, uint32_t& lo) {
    __half h0 = __float2half_rn(e0), h1 = __float2half_rn(e1);
    __half l0 = __float2half_rn(e0 - __half2float(h0));
    __half l1 = __float2half_rn(e1 - __half2float(h1));
    __half2 hp = __halves2half2(h0, h1);
    __half2 lp = __halves2half2(l0, l1);
    hi = *reinterpret_cast<uint32_t*>(&hp);
    lo = *reinterpret_cast<uint32_t*>(&lp);
}
__device__ __forceinline__ void mma16816h(float* c, const uint32_t* a, const uint32_t* b) {
    asm volatile(
        "mma.sync.aligned.m16n8k16.row.col.f32.f16.f16.f32 "
        "{%0,%1,%2,%3}, {%4,%5,%6,%7}, {%8,%9}, {%0,%1,%2,%3};\n"
        : "+f"(c[0]), "+f"(c[1]), "+f"(c[2]), "+f"(c[3])
        : "r"(a[0]), "r"(a[1]), "r"(a[2]), "r"(a[3]), "r"(b[0]), "r"(b[1]));
}
__device__ __forceinline__ void ldfrag(uint32_t* r, uint32_t base, int row0, int kb, int lane) {
    int rl = row0 + (lane & 15);
    int cb = kb + ((lane >> 4) << 4);
    uint32_t a = base + (uint32_t)SW128(rl * 128 + cb);
    asm volatile("ldmatrix.sync.aligned.m8n8.x4.shared.b16 {%0,%1,%2,%3}, [%4];"
                 : "=r"(r[0]), "=r"(r[1]), "=r"(r[2]), "=r"(r[3]) : "r"(a));
}
// 2-term chunk: acc += (Ah + Al) * Bh
__device__ __forceinline__ void mma_chunk2(
    float (*acc)[8][4], uint32_t Ah, uint32_t Al, uint32_t Bh,
    int lane, int wm, int wn)
{
#pragma unroll
    for (int ks = 0; ks < 4; ks++) {
        const int kb = ks * 32;
        uint32_t ah[2][4], al[2][4];
        ldfrag(ah[0], Ah, wm,      kb, lane);
        ldfrag(ah[1], Ah, wm + 16, kb, lane);
        ldfrag(al[0], Al, wm,      kb, lane);
        ldfrag(al[1], Al, wm + 16, kb, lane);
#pragma unroll
        for (int j = 0; j < 4; j++) {
            uint32_t bh[4];
            ldfrag(bh, Bh, wn + j * 16, kb, lane);
            uint32_t b0h[2] = {bh[0], bh[2]}, b1h[2] = {bh[1], bh[3]};
#pragma unroll
            for (int i = 0; i < 2; i++) {
                mma16816h(acc[i][2 * j],     ah[i], b0h);
                mma16816h(acc[i][2 * j],     al[i], b0h);
                mma16816h(acc[i][2 * j + 1], ah[i], b1h);
                mma16816h(acc[i][2 * j + 1], al[i], b1h);
            }
        }
    }
}
// 3-term chunk: acc += Ah*Bh + Ah*Bl + Al*Bh
__device__ __forceinline__ void mma_chunk3(
    float (*acc)[8][4], uint32_t Ah, uint32_t Al, uint32_t Bh, uint32_t Bl,
    int lane, int wm, int wn)
{
#pragma unroll
    for (int ks = 0; ks < 4; ks++) {
        const int kb = ks * 32;
        uint32_t ah[2][4], al[2][4];
        ldfrag(ah[0], Ah, wm,      kb, lane);
        ldfrag(ah[1], Ah, wm + 16, kb, lane);
        ldfrag(al[0], Al, wm,      kb, lane);
        ldfrag(al[1], Al, wm + 16, kb, lane);
#pragma unroll
        for (int j = 0; j < 4; j++) {
            uint32_t bh[4], bl[4];
            ldfrag(bh, Bh, wn + j * 16, kb, lane);
            ldfrag(bl, Bl, wn + j * 16, kb, lane);
            uint32_t b0h[2] = {bh[0], bh[2]}, b1h[2] = {bh[1], bh[3]};
            uint32_t b0l[2] = {bl[0], bl[2]}, b1l[2] = {bl[1], bl[3]};
#pragma unroll
            for (int i = 0; i < 2; i++) {
                mma16816h(acc[i][2 * j],     ah[i], b0h);
                mma16816h(acc[i][2 * j],     ah[i], b0l);
                mma16816h(acc[i][2 * j],     al[i], b0h);
                mma16816h(acc[i][2 * j + 1], ah[i], b1h);
                mma16816h(acc[i][2 * j + 1], ah[i], b1l);
                mma16816h(acc[i][2 * j + 1], al[i], b1h);
            }
        }
    }
}
__device__ __forceinline__ void cp16(uint32_t dst, const void* src) {
    asm volatile("cp.async.cg.shared.global [%0], [%1], 16;"
                 :: "r"(dst), "l"((unsigned long long)__cvta_generic_to_global(src)) : "memory");
}
__device__ __forceinline__ void cp_commit() {
    asm volatile("cp.async.commit_group;" ::: "memory");
}
template <int N>
__device__ __forceinline__ void cp_wait() {
    asm volatile("cp.async.wait_group %0;" :: "n"(N) : "memory");
}

// ---------------------------------------------------------------------------
// K0a: W split -> swizzled fp16 hi/lo planes. grid 24, 256 thr.
// ---------------------------------------------------------------------------
__global__ __launch_bounds__(256) void wsplit(
    const float* __restrict__ Wq, const float* __restrict__ Wk,
    const float* __restrict__ Wv)
{
    const int p = blockIdx.x >> 3, rem = blockIdx.x & 7;
    const int mh = rem >> 2, kt = rem & 3;
    const float* W = (p == 0) ? Wq : (p == 1) ? Wk : Wv;
    const int m0 = mh * 128, k0 = kt * 64;
    char* dh = (char*)g_Wsp[p][mh][kt][0];
    char* dl = (char*)g_Wsp[p][mh][kt][1];
    const int tid = threadIdx.x;
#pragma unroll
    for (int i = 0; i < 16; i++) {
        int idx = i * 256 + tid;
        int r = idx >> 5, k2 = idx & 31;
        float2 w2 = *(const float2*)&W[(size_t)(m0 + r) * C + k0 + 2 * k2];
        uint32_t hi, lo; split2h(w2.x, w2.y, hi, lo);
        int off = SW128(r * 128 + k2 * 4);
        *(uint32_t*)(dh + off) = hi;
        *(uint32_t*)(dl + off) = lo;
    }
}

// ---------------------------------------------------------------------------
// K0b: x -> fp16 hi plane only, transposed + swizzled. grid (32,4,8), 256 thr.
// ---------------------------------------------------------------------------
__global__ __launch_bounds__(256) void xsplit(const float* __restrict__ x)
{
    __shared__ float xs[64][129];
    const int nt = blockIdx.x, kt = blockIdx.y, b = blockIdx.z;
    const int n0 = nt * 128, c0 = kt * 64;
    const int tid = threadIdx.x;
    const float* xb = x + (size_t)b * C * HW;

#pragma unroll
    for (int i = 0; i < 8; i++) {
        int idx = i * 256 + tid;          // float4 index
        int c = idx >> 5, f4 = idx & 31;
        float4 v = *(const float4*)&xb[(size_t)(c0 + c) * HW + n0 + f4 * 4];
        xs[c][f4 * 4 + 0] = v.x; xs[c][f4 * 4 + 1] = v.y;
        xs[c][f4 * 4 + 2] = v.z; xs[c][f4 * 4 + 3] = v.w;
    }
    __syncthreads();

    char* dh = (char*)g_Xsp[b][nt][kt];
#pragma unroll
    for (int i = 0; i < 16; i++) {
        int idx = i * 256 + tid;
        int n = idx >> 5, k2 = idx & 31;
        __half2 hp = __floats2half2_rn(xs[2 * k2][n], xs[2 * k2 + 1][n]);
        *(uint32_t*)(dh + SW128(n * 128 + k2 * 4)) = *reinterpret_cast<uint32_t*>(&hp);
    }
}

// ---------------------------------------------------------------------------
// K1: proj, 2-term.  grid (32, 2, 24), 256 thr, 96KB smem (2 CTA/SM).
// ---------------------------------------------------------------------------
__global__ __launch_bounds__(256, 2) void proj_gemm(
    const float* __restrict__ bq, const float* __restrict__ bk,
    const float* __restrict__ bv)
{
    extern __shared__ char smraw[];
    uint32_t sa0 = smaddr(smraw);
    char* sm = smraw + ((1024u - (sa0 & 1023u)) & 1023u);
    const uint32_t sb = smaddr(sm);   // [buf][Ah,Al,Bh][PLANE]

    const int p = blockIdx.z >> 3, b = blockIdx.z & 7;
    const float* bias = (p == 0) ? bq : (p == 1) ? bk : bv;
    const int tid = threadIdx.x, lane = tid & 31, wid = tid >> 5;
    const int nt = blockIdx.x, mh = blockIdx.y;
    const int n0 = nt * 128, m0 = mh * 128;
    const int wm = (wid & 3) * 32, wn = (wid >> 2) * 64;

    auto stage = [&](int kt, int t) {
        const uint32_t base = sb + t * 3 * PLANE;
        const uint32_t* Ah = g_Wsp[p][mh][kt][0];
        const uint32_t* Al = g_Wsp[p][mh][kt][1];
        const uint32_t* Bh = g_Xsp[b][nt][kt];
#pragma unroll
        for (int i = 0; i < 4; i++) {
            int idx = i * 256 + tid;
            uint32_t doff = idx * 16;
            cp16(base + doff,             Ah + idx * 4);
            cp16(base + PLANE + doff,     Al + idx * 4);
            cp16(base + 2 * PLANE + doff, Bh + idx * 4);
        }
        cp_commit();
    };

    stage(0, 0);
    float acc[2][8][4] = {};
#pragma unroll
    for (int kt = 0; kt < 4; kt++) {
        if (kt < 3) { stage(kt + 1, (kt + 1) & 1); cp_wait<1>(); }
        else        { cp_wait<0>(); }
        __syncthreads();
        const uint32_t base = sb + (kt & 1) * 3 * PLANE;
        mma_chunk2(acc, base, base + PLANE, base + 2 * PLANE, lane, wm, wn);
        __syncthreads();
    }

    // epilogue: +bias, plane stores (lo only for p>=1), per-row partial stats
    const int g = lane >> 2, tg = lane & 3;
    float rsum[4] = {}, rsum2[4] = {};
#pragma unroll
    for (int i = 0; i < 2; i++)
#pragma unroll
        for (int j = 0; j < 8; j++) {
            int r0 = m0 + wm + i * 16 + g;
            int cc = n0 + wn + j * 8 + tg * 2;
            uint32_t hi, lo;
            float bi = bias[r0];
            float y0 = acc[i][j][0] + bi, y1 = acc[i][j][1] + bi;
            rsum[i * 2]  += y0 + y1;
            rsum2[i * 2] += y0 * y0 + y1 * y1;
            split2h(y0, y1, hi, lo);
            size_t off = ((size_t)(b * C + r0) * HW + cc) >> 1;
            g_Yhi[p][off] = hi;
            if (p) g_Ylo[p][off] = lo;
            int r1 = r0 + 8;
            bi = bias[r1];
            y0 = acc[i][j][2] + bi; y1 = acc[i][j][3] + bi;
            rsum[i * 2 + 1]  += y0 + y1;
            rsum2[i * 2 + 1] += y0 * y0 + y1 * y1;
            split2h(y0, y1, hi, lo);
            off = ((size_t)(b * C + r1) * HW + cc) >> 1;
            g_Yhi[p][off] = hi;
            if (p) g_Ylo[p][off] = lo;
        }
#pragma unroll
    for (int q = 0; q < 4; q++) {
        rsum[q]  += __shfl_xor_sync(0xffffffffu, rsum[q], 1);
        rsum[q]  += __shfl_xor_sync(0xffffffffu, rsum[q], 2);
        rsum2[q] += __shfl_xor_sync(0xffffffffu, rsum2[q], 1);
        rsum2[q] += __shfl_xor_sync(0xffffffffu, rsum2[q], 2);
    }
    float* sbf  = (float*)sm;
    float* sbf2 = (float*)(sm + 2048);
    if (tg == 0) {
        const int half = wn >> 6;
#pragma unroll
        for (int q = 0; q < 4; q++) {
            int r = wm + (q >> 1) * 16 + (q & 1) * 8 + g;
            sbf[r * 2 + half]  = rsum[q];
            sbf2[r * 2 + half] = rsum2[q];
        }
    }
    __syncthreads();
    if (tid < 128) {
        size_t off = ((size_t)b * NT + nt) * C + m0 + tid;
        g_Psum[p][off]  = sbf[tid * 2] + sbf[tid * 2 + 1];
        g_Psum2[p][off] = sbf2[tid * 2] + sbf2[tid * 2 + 1];
    }
}

// ---------------------------------------------------------------------------
// K2: BN affine from partial stats. grid 3*C, 256.
// ---------------------------------------------------------------------------
__global__ __launch_bounds__(256) void bn_stats(
    const float* __restrict__ gq, const float* __restrict__ betaq,
    const float* __restrict__ gk, const float* __restrict__ betak,
    const float* __restrict__ gv, const float* __restrict__ betav)
{
    __shared__ float bs[8], bs2[8];
    const int p = blockIdx.x / C, c = blockIdx.x % C;
    const int lane = threadIdx.x & 31, b = threadIdx.x >> 5;

    size_t off = ((size_t)b * NT + lane) * C + c;
    float s  = g_Psum[p][off];
    float s2 = g_Psum2[p][off];
#pragma unroll
    for (int o = 16; o > 0; o >>= 1) {
        s  += __shfl_xor_sync(0xffffffffu, s, o);
        s2 += __shfl_xor_sync(0xffffffffu, s2, o);
    }
    if (lane == 0) {
        g_S[p][b * C + c] = s;
        bs[b] = s; bs2[b] = s2;
    }
    __syncthreads();
    if (threadIdx.x == 0) {
        float ts = 0.f, ts2 = 0.f;
#pragma unroll
        for (int i = 0; i < 8; i++) { ts += bs[i]; ts2 += bs2[i]; }
        const float inv_n = 1.f / (float)(B * HW);
        float mu  = ts * inv_n;
        float var = ts2 * inv_n - mu * mu;
        float inv = rsqrtf(var + BN_EPS);
        const float* gg = (p == 0) ? gq : (p == 1) ? gk : gv;
        const float* be = (p == 0) ? betaq : (p == 1) ? betak : betav;
        float a = gg[c] * inv;
        g_a[p][c] = a;
        g_d[p][c] = be[c] - mu * a;
    }
}

// ---------------------------------------------------------------------------
// K3: Gram = V * K^T, 3-term, split-K=16. grid (2,2,128), 256 thr, 128KB smem.
// ---------------------------------------------------------------------------
__global__ __launch_bounds__(256, 1) void gram_gemm()
{
    extern __shared__ char smraw[];
    uint32_t sa0 = smaddr(smraw);
    char* sm = smraw + ((1024u - (sa0 & 1023u)) & 1023u);
    const uint32_t sb = smaddr(sm);

    const int tid = threadIdx.x, lane = tid & 31, wid = tid >> 5;
    const int s = blockIdx.z >> 3, b = blockIdx.z & 7;
    const int m0 = blockIdx.y * 128, n0 = blockIdx.x * 128;
    const int wm = (wid & 3) * 32, wn = (wid >> 2) * 64;

    const uint32_t* Vh = g_Yhi[2] + (size_t)b * C * (HW / 2);
    const uint32_t* Vl = g_Ylo[2] + (size_t)b * C * (HW / 2);
    const uint32_t* Kh = g_Yhi[1] + (size_t)b * C * (HW / 2);
    const uint32_t* Kl = g_Ylo[1] + (size_t)b * C * (HW / 2);

    auto stage = [&](int kt, int t) {
        const int kw = s * 128 + kt * 32;
        const uint32_t base = sb + t * 4 * PLANE;
#pragma unroll
        for (int i = 0; i < 4; i++) {
            int idx = i * 256 + tid;
            int r = idx >> 3, u = idx & 7;
            uint32_t doff = (uint32_t)SW128(r * 128 + u * 16);
            size_t sA = (size_t)(m0 + r) * (HW / 2) + kw + u * 4;
            size_t sB = (size_t)(n0 + r) * (HW / 2) + kw + u * 4;
            cp16(base + doff,             Vh + sA);
            cp16(base + PLANE + doff,     Vl + sA);
            cp16(base + 2 * PLANE + doff, Kh + sB);
            cp16(base + 3 * PLANE + doff, Kl + sB);
        }
        cp_commit();
    };

    stage(0, 0);
    float acc[2][8][4] = {};
#pragma unroll
    for (int kt = 0; kt < 4; kt++) {
        if (kt < 3) { stage(kt + 1, (kt + 1) & 1); cp_wait<1>(); }
        else        { cp_wait<0>(); }
        __syncthreads();
        const uint32_t base = sb + (kt & 1) * 4 * PLANE;
        mma_chunk3(acc, base, base + PLANE, base + 2 * PLANE, base + 3 * PLANE,
                   lane, wm, wn);
        __syncthreads();
    }

    float* Gp = &g_Gpart[s][(size_t)b * C * C];
    const int g = lane >> 2, tg = lane & 3;
#pragma unroll
    for (int i = 0; i < 2; i++)
#pragma unroll
        for (int j = 0; j < 8; j++) {
            int r0 = m0 + wm + i * 16 + g;
            int cc = n0 + wn + j * 8 + tg * 2;
            *(float2*)&Gp[(size_t)r0 * C + cc] = make_float2(acc[i][j][0], acc[i][j][1]);
            *(float2*)&Gp[(size_t)(r0 + 8) * C + cc] = make_float2(acc[i][j][2], acc[i][j][3]);
        }
}

// ---------------------------------------------------------------------------
// K4: reduce Gram partials + BN fold -> fp16 M2 planes + r.  grid (C,B), 256.
// ---------------------------------------------------------------------------
__global__ __launch_bounds__(256) void m_fix()
{
    __shared__ float red[256];
    const int m = blockIdx.x, b = blockIdx.y;
    const int c = threadIdx.x;
    __half* M2h = reinterpret_cast<__half*>(g_M2hi);
    __half* M2l = reinterpret_cast<__half*>(g_M2lo);

    const float av = g_a[2][m], dv = g_d[2][m];
    const float SV = g_S[2][b * C + m];

    const size_t rowoff = (size_t)b * C * C + (size_t)m * C + c;
    float e = 0.f;
#pragma unroll
    for (int s = 0; s < SPLIT; s++)
        e += g_Gpart[s][rowoff];

    float ak = g_a[1][c], dk = g_d[1][c];
    float SK = g_S[1][b * C + c];
    float M = av * ak * e + av * dk * SV + dv * ak * SK + 4096.f * dv * dk;
    float M2 = 0.125f * M * g_a[0][c];
    __half hi = __float2half_rn(M2);
    __half lo = __float2half_rn(M2 - __half2float(hi));
    size_t off = (size_t)(b * C + m) * C + c;
    M2h[off] = hi; M2l[off] = lo;

    red[c] = M * g_d[0][c];
    __syncthreads();
    for (int o = 128; o > 0; o >>= 1) {
        if (c < o) red[c] += red[c + o];
        __syncthreads();
    }
    if (c == 0) g_r[b * C + m] = 0.125f * red[0];
}

// ---------------------------------------------------------------------------
// K5: out = (M2h+M2l) * Qh + r, 2-term.  grid (32, 2, 8), 256 thr, 96KB smem.
// ---------------------------------------------------------------------------
__global__ __launch_bounds__(256) void out_gemm(float* __restrict__ out)
{
    extern __shared__ char smraw[];
    uint32_t sa0 = smaddr(smraw);
    char* sm = smraw + ((1024u - (sa0 & 1023u)) & 1023u);
    const uint32_t sbA = smaddr(sm);                  // [buf][hi,lo][PLANE]
    const uint32_t sbB = sbA + 4 * PLANE;             // [buf][PLANE]
    char* smB = sm + 4 * PLANE;

    const int tid = threadIdx.x, lane = tid & 31, wid = tid >> 5;
    const int b = blockIdx.z;
    const int n0 = blockIdx.x * 128, m0 = blockIdx.y * 128;
    const int wm = (wid & 3) * 32, wn = (wid >> 2) * 64;

    const uint32_t* Qh = g_Yhi[0] + (size_t)b * C * (HW / 2);

    auto stageA = [&](int kt, int t) {
        const uint32_t base = sbA + t * 2 * PLANE;
#pragma unroll
        for (int i = 0; i < 4; i++) {
            int idx = i * 256 + tid;
            int r = idx >> 3, u = idx & 7;
            uint32_t doff = (uint32_t)SW128(r * 128 + u * 16);
            size_t srco = (size_t)(b * C + m0 + r) * (C / 2) + kt * 32 + u * 4;
            cp16(base + doff,         g_M2hi + srco);
            cp16(base + PLANE + doff, g_M2lo + srco);
        }
        cp_commit();
    };

    uint32_t bu0[2][8], bu1[2][8];
    auto ldgB = [&](int kt, int t) {
        const int k0 = kt * 64;
#pragma unroll
        for (int i = 0; i < 8; i++) {
            int idx = i * 256 + tid;
            int k2 = idx >> 6, np = idx & 63;
            size_t srco = (size_t)(k0 + 2 * k2) * (HW / 2) + (n0 >> 1) + np;
            bu0[t][i] = Qh[srco]; bu1[t][i] = Qh[srco + HW / 2];
        }
    };
    auto stsB = [&](int t) {
        char* base = smB + t * PLANE;
#pragma unroll
        for (int i = 0; i < 8; i++) {
            int idx = i * 256 + tid;
            int k2 = idx >> 6, np = idx & 63;
            int offE = SW128((2 * np) * 128 + k2 * 4);
            int offO = SW128((2 * np + 1) * 128 + k2 * 4);
            *(uint32_t*)(base + offE) = __byte_perm(bu0[t][i], bu1[t][i], 0x5410);
            *(uint32_t*)(base + offO) = __byte_perm(bu0[t][i], bu1[t][i], 0x7632);
        }
    };

    ldgB(0, 0);
    stageA(0, 0);
    float acc[2][8][4] = {};
#pragma unroll
    for (int kt = 0; kt < 4; kt++) {
        stsB(kt & 1);
        if (kt < 3) {
            ldgB(kt + 1, (kt + 1) & 1);
            stageA(kt + 1, (kt + 1) & 1);
            cp_wait<1>();
        } else {
            cp_wait<0>();
        }
        __syncthreads();
        const uint32_t bA = sbA + (kt & 1) * 2 * PLANE;
        const uint32_t bB = sbB + (kt & 1) * PLANE;
        mma_chunk2(acc, bA, bA + PLANE, bB, lane, wm, wn);
        __syncthreads();
    }

    const int g = lane >> 2, tg = lane & 3;
#pragma unroll
    for (int i = 0; i < 2; i++)
#pragma unroll
        for (int j = 0; j < 8; j++) {
            int r0 = m0 + wm + i * 16 + g;
            int cc = n0 + wn + j * 8 + tg * 2;
            float rr = g_r[b * C + r0];
            *(float2*)&out[(size_t)(b * C + r0) * HW + cc] =
                make_float2(acc[i][j][0] + rr, acc[i][j][1] + rr);
            rr = g_r[b * C + r0 + 8];
            *(float2*)&out[(size_t)(b * C + r0 + 8) * HW + cc] =
                make_float2(acc[i][j][2] + rr, acc[i][j][3] + rr);
        }
}

// ---------------------------------------------------------------------------
extern "C" void kernel_launch(void* const* d_in, const int* in_sizes, int n_in,
                              void* d_out, int out_size)
{
    const float* x     = (const float*)d_in[0];
    const float* Wq    = (const float*)d_in[1];
    const float* bq    = (const float*)d_in[2];
    const float* gq    = (const float*)d_in[3];
    const float* betaq = (const float*)d_in[4];
    const float* Wk    = (const float*)d_in[5];
    const float* bk    = (const float*)d_in[6];
    const float* gk    = (const float*)d_in[7];
    const float* betak = (const float*)d_in[8];
    const float* Wv    = (const float*)d_in[9];
    const float* bv    = (const float*)d_in[10];
    const float* gv    = (const float*)d_in[11];
    const float* betav = (const float*)d_in[12];
    float* out = (float*)d_out;

    const int smSix  = 6 * PLANE + 1024;   // proj, out
    const int smGram = 8 * PLANE + 1024;   // gram
    cudaFuncSetAttribute(proj_gemm, cudaFuncAttributeMaxDynamicSharedMemorySize, smSix);
    cudaFuncSetAttribute(gram_gemm, cudaFuncAttributeMaxDynamicSharedMemorySize, smGram);
    cudaFuncSetAttribute(out_gemm,  cudaFuncAttributeMaxDynamicSharedMemorySize, smSix);

    wsplit<<<24, 256>>>(Wq, Wk, Wv);
    xsplit<<<dim3(NT, 4, B), 256>>>(x);
    proj_gemm<<<dim3(32, 2, 3 * B), 256, smSix>>>(bq, bk, bv);
    bn_stats<<<3 * C, 256>>>(gq, betaq, gk, betak, gv, betav);
    gram_gemm<<<dim3(2, 2, SPLIT * B), 256, smGram>>>();
    m_fix<<<dim3(C, B), 256>>>();
    out_gemm<<<dim3(32, 2, B), 256, smSix>>>(out);
}